// round 4
// baseline (speedup 1.0000x reference)
#include <cuda_runtime.h>
#include <math.h>

#define Bsz 8
#define Dd 512
#define Hh 8
#define Ee 64
#define DI 1024
#define Ss 64
#define Rr 32
#define DFF 2048
#define LL 1152
#define Mrows (Bsz*LL)   /* 9216 */

// ---------------- scratch (static __device__, no allocation) ----------------
__device__ float g_q[Mrows*Dd];
__device__ float g_k[Mrows*Dd];
__device__ float g_v[Mrows*Dd];
__device__ float g_attnO[Mrows*Dd];
__device__ float g_attn_out[Mrows*Dd];
__device__ float g_xz[Mrows*2*DI];
__device__ float g_uact[Mrows*DI];
__device__ float g_xdbc[Mrows*160];
__device__ float g_delta[Mrows*DI];
__device__ float g_y[Mrows*DI];
__device__ float g_mamba[Mrows*Dd];
__device__ float g_h[Mrows*Dd];
__device__ float g_hn[Mrows*Dd];
__device__ float g_mid[Mrows*DFF];

// ---------------- generic SGEMM: C = A(MxK, lda) @ W(NxK)^T (+bias, +epi) ----
enum { EPI_NONE = 0, EPI_SOFTPLUS = 1, EPI_GELU = 2, EPI_ADD = 3 };

template<int EPI>
__global__ __launch_bounds__(256) void sgemm_k(
    const float* __restrict__ A, int lda,
    const float* __restrict__ W,
    const float* __restrict__ bias,
    const float* __restrict__ add,
    float* __restrict__ C, int M, int N, int K)
{
    __shared__ float As[8][128];
    __shared__ float Ws[8][64];
    int tid = threadIdx.x;
    int tx = tid & 15, ty = tid >> 4;
    int m0 = blockIdx.y * 128, n0 = blockIdx.x * 64;

    float acc[8][4];
#pragma unroll
    for (int i = 0; i < 8; i++)
#pragma unroll
        for (int j = 0; j < 4; j++) acc[i][j] = 0.f;

    int arow = tid >> 1;
    int akq  = (tid & 1) * 4;
    const float* Aptr = A + (size_t)(m0 + arow) * lda + akq;
    int wrow = (tid & 127) >> 1;
    int wkq  = (tid & 1) * 4;
    bool wvalid = (tid < 128) && (n0 + wrow < N);
    const float* Wptr = W + (size_t)(n0 + wrow) * K + wkq;

    for (int k0 = 0; k0 < K; k0 += 8) {
        float4 av = *(const float4*)(Aptr + k0);
        As[akq+0][arow] = av.x; As[akq+1][arow] = av.y;
        As[akq+2][arow] = av.z; As[akq+3][arow] = av.w;
        if (tid < 128) {
            float4 wv = make_float4(0.f, 0.f, 0.f, 0.f);
            if (wvalid) wv = *(const float4*)(Wptr + k0);
            Ws[wkq+0][wrow] = wv.x; Ws[wkq+1][wrow] = wv.y;
            Ws[wkq+2][wrow] = wv.z; Ws[wkq+3][wrow] = wv.w;
        }
        __syncthreads();
#pragma unroll
        for (int kk = 0; kk < 8; kk++) {
            float4 a0 = *(const float4*)&As[kk][ty*8];
            float4 a1 = *(const float4*)&As[kk][ty*8+4];
            float4 b0 = *(const float4*)&Ws[kk][tx*4];
            float ar[8] = {a0.x,a0.y,a0.z,a0.w,a1.x,a1.y,a1.z,a1.w};
            float br[4] = {b0.x,b0.y,b0.z,b0.w};
#pragma unroll
            for (int i = 0; i < 8; i++)
#pragma unroll
                for (int j = 0; j < 4; j++)
                    acc[i][j] = fmaf(ar[i], br[j], acc[i][j]);
        }
        __syncthreads();
    }

#pragma unroll
    for (int i = 0; i < 8; i++) {
        int m = m0 + ty*8 + i;
#pragma unroll
        for (int j = 0; j < 4; j++) {
            int n = n0 + tx*4 + j;
            if (n < N) {
                float vv = acc[i][j];
                if (bias) vv += bias[n];
                if (EPI == EPI_SOFTPLUS) {
                    vv = (vv > 20.f) ? vv : log1pf(expf(vv));
                } else if (EPI == EPI_GELU) {
                    vv = 0.5f * vv * (1.f + erff(vv * 0.7071067811865475f));
                } else if (EPI == EPI_ADD) {
                    vv += add[(size_t)m * N + n];
                }
                C[(size_t)m * N + n] = vv;
            }
        }
    }
}

// ---------------- flash attention: 64-row Q tile, 32-key tiles ---------------
__global__ __launch_bounds__(256) void attn_k(
    const float* __restrict__ q, const float* __restrict__ k,
    const float* __restrict__ v, const unsigned char* __restrict__ mask,
    float* __restrict__ o)
{
    __shared__ float QsT[64][64];   // [e][m]
    __shared__ float KsT[64][32];   // [e][n]
    __shared__ float Vs [32][64];   // [n][e]
    __shared__ float PsT[32][68];   // [n][m] (padded)

    int qt = blockIdx.x, h = blockIdx.y, b = blockIdx.z;
    int tid = threadIdx.x;
    int tx = tid & 15, ty = tid >> 4;
    const size_t bL = (size_t)b * LL;
    int q0 = qt * 64;

    for (int i = tid; i < 1024; i += 256) {
        int m = i >> 4, e4 = (i & 15) * 4;
        float4 qv = *(const float4*)&q[(bL + q0 + m) * Dd + h*Ee + e4];
        QsT[e4+0][m] = qv.x; QsT[e4+1][m] = qv.y;
        QsT[e4+2][m] = qv.z; QsT[e4+3][m] = qv.w;
    }

    float acc[4][4];
#pragma unroll
    for (int i = 0; i < 4; i++)
#pragma unroll
        for (int j = 0; j < 4; j++) acc[i][j] = 0.f;
    float mrow[4] = {-INFINITY, -INFINITY, -INFINITY, -INFINITY};
    float lrow[4] = {0.f, 0.f, 0.f, 0.f};
    const float scale = 0.125f;   // 1/sqrt(64)

    for (int n0k = 0; n0k < LL; n0k += 32) {
        __syncthreads();
        for (int i = tid; i < 512; i += 256) {
            int n = i >> 4, e4 = (i & 15) * 4;
            size_t gr = (bL + n0k + n) * Dd + h*Ee + e4;
            float4 kv = *(const float4*)&k[gr];
            KsT[e4+0][n] = kv.x; KsT[e4+1][n] = kv.y;
            KsT[e4+2][n] = kv.z; KsT[e4+3][n] = kv.w;
            float4 vv = *(const float4*)&v[gr];
            *(float4*)&Vs[n][e4] = vv;
        }
        __syncthreads();

        float s[4][2];
#pragma unroll
        for (int i = 0; i < 4; i++) { s[i][0] = 0.f; s[i][1] = 0.f; }
#pragma unroll 16
        for (int e = 0; e < 64; e++) {
            float4 qv = *(const float4*)&QsT[e][ty*4];
            float2 kv = *(const float2*)&KsT[e][tx*2];
            s[0][0] = fmaf(qv.x, kv.x, s[0][0]); s[0][1] = fmaf(qv.x, kv.y, s[0][1]);
            s[1][0] = fmaf(qv.y, kv.x, s[1][0]); s[1][1] = fmaf(qv.y, kv.y, s[1][1]);
            s[2][0] = fmaf(qv.z, kv.x, s[2][0]); s[2][1] = fmaf(qv.z, kv.y, s[2][1]);
            s[3][0] = fmaf(qv.w, kv.x, s[3][0]); s[3][1] = fmaf(qv.w, kv.y, s[3][1]);
        }

        unsigned char mk0 = mask[bL + n0k + tx*2 + 0];
        unsigned char mk1 = mask[bL + n0k + tx*2 + 1];
        float p[4][2];
#pragma unroll
        for (int i = 0; i < 4; i++) {
            float s0 = s[i][0] * scale, s1 = s[i][1] * scale;
            if (mk0) s0 = -INFINITY;
            if (mk1) s1 = -INFINITY;
            float t = fmaxf(s0, s1);
#pragma unroll
            for (int off = 1; off < 16; off <<= 1)
                t = fmaxf(t, __shfl_xor_sync(0xffffffffu, t, off));
            float mnew = fmaxf(mrow[i], t);
            float p0 = __expf(s0 - mnew), p1 = __expf(s1 - mnew);
            float rs = p0 + p1;
#pragma unroll
            for (int off = 1; off < 16; off <<= 1)
                rs += __shfl_xor_sync(0xffffffffu, rs, off);
            float corr = __expf(mrow[i] - mnew);
            lrow[i] = lrow[i] * corr + rs;
            mrow[i] = mnew;
            acc[i][0] *= corr; acc[i][1] *= corr;
            acc[i][2] *= corr; acc[i][3] *= corr;
            p[i][0] = p0; p[i][1] = p1;
        }
#pragma unroll
        for (int j = 0; j < 2; j++) {
            int n = tx*2 + j;
            *(float4*)&PsT[n][ty*4] = make_float4(p[0][j], p[1][j], p[2][j], p[3][j]);
        }
        __syncthreads();
#pragma unroll 8
        for (int n = 0; n < 32; n++) {
            float4 pv = *(const float4*)&PsT[n][ty*4];
            float4 vv = *(const float4*)&Vs[n][tx*4];
            acc[0][0] = fmaf(pv.x, vv.x, acc[0][0]); acc[0][1] = fmaf(pv.x, vv.y, acc[0][1]);
            acc[0][2] = fmaf(pv.x, vv.z, acc[0][2]); acc[0][3] = fmaf(pv.x, vv.w, acc[0][3]);
            acc[1][0] = fmaf(pv.y, vv.x, acc[1][0]); acc[1][1] = fmaf(pv.y, vv.y, acc[1][1]);
            acc[1][2] = fmaf(pv.y, vv.z, acc[1][2]); acc[1][3] = fmaf(pv.y, vv.w, acc[1][3]);
            acc[2][0] = fmaf(pv.z, vv.x, acc[2][0]); acc[2][1] = fmaf(pv.z, vv.y, acc[2][1]);
            acc[2][2] = fmaf(pv.z, vv.z, acc[2][2]); acc[2][3] = fmaf(pv.z, vv.w, acc[2][3]);
            acc[3][0] = fmaf(pv.w, vv.x, acc[3][0]); acc[3][1] = fmaf(pv.w, vv.y, acc[3][1]);
            acc[3][2] = fmaf(pv.w, vv.z, acc[3][2]); acc[3][3] = fmaf(pv.w, vv.w, acc[3][3]);
        }
    }

#pragma unroll
    for (int i = 0; i < 4; i++) {
        float inv = 1.f / lrow[i];
        size_t row = (bL + q0 + ty*4 + i) * Dd + h*Ee + tx*4;
        *(float4*)&o[row] = make_float4(acc[i][0]*inv, acc[i][1]*inv,
                                        acc[i][2]*inv, acc[i][3]*inv);
    }
}

// ---------------- causal depthwise conv (KC=4) + SiLU ------------------------
__global__ void conv_silu_k(const float* __restrict__ xz,
                            const float* __restrict__ cw,
                            const float* __restrict__ cb,
                            float* __restrict__ uact)
{
    int idx = blockIdx.x * 256 + threadIdx.x;     // over Mrows*DI
    int r = idx >> 10;
    int j = idx & 1023;
    int t = r % LL;
    float acc = cb[j];
#pragma unroll
    for (int kk = 0; kk < 4; kk++) {
        int tt = t + kk - 3;
        if (tt >= 0)
            acc = fmaf(xz[(size_t)(r + kk - 3) * (2*DI) + j], cw[j*4 + kk], acc);
    }
    uact[idx] = acc / (1.f + expf(-acc));
}

// ---------------- selective scan: 1 warp per (b,d), 2 states/lane ------------
__global__ __launch_bounds__(512) void scan_k(
    const float* __restrict__ delta, const float* __restrict__ uact,
    const float* __restrict__ xdbc, const float* __restrict__ A_log,
    float* __restrict__ y)
{
    __shared__ float sB[16][64];
    __shared__ float sC[16][64];
    __shared__ float sdt[16][16];
    __shared__ float su[16][16];

    int b = blockIdx.y;
    int d0 = blockIdx.x * 16;
    int tid = threadIdx.x;
    int w = tid >> 5, l = tid & 31;
    int d = d0 + w;
    float a0 = -expf(A_log[d*Ss + l]);
    float a1 = -expf(A_log[d*Ss + l + 32]);
    float h0 = 0.f, h1 = 0.f;
    size_t base = (size_t)b * LL;

    for (int t0 = 0; t0 < LL; t0 += 16) {
        __syncthreads();
        for (int i = tid; i < 2048; i += 512) {
            int tt = i >> 7, c = i & 127;
            float val = xdbc[(base + t0 + tt) * 160 + 32 + c];
            if (c < 64) sB[tt][c] = val; else sC[tt][c - 64] = val;
        }
        if (tid < 256) {
            sdt[tid >> 4][tid & 15] = delta[(base + t0 + (tid >> 4)) * DI + d0 + (tid & 15)];
        } else {
            int jj = tid - 256;
            su[jj >> 4][jj & 15] = uact[(base + t0 + (jj >> 4)) * DI + d0 + (jj & 15)];
        }
        __syncthreads();
#pragma unroll 4
        for (int tt = 0; tt < 16; tt++) {
            float dt  = sdt[tt][w];
            float dtu = dt * su[tt][w];
            float dA0 = __expf(dt * a0);
            float dA1 = __expf(dt * a1);
            h0 = fmaf(h0, dA0, dtu * sB[tt][l]);
            h1 = fmaf(h1, dA1, dtu * sB[tt][l + 32]);
            float yv = h0 * sC[tt][l] + h1 * sC[tt][l + 32];
#pragma unroll
            for (int off = 16; off > 0; off >>= 1)
                yv += __shfl_xor_sync(0xffffffffu, yv, off);
            if (l == 0) y[(base + t0 + tt) * DI + d] = yv;
        }
    }
}

// ---------------- gate: y = (y + uact*D) * silu(z) ---------------------------
__global__ void gate_k(float* __restrict__ y, const float* __restrict__ uact,
                       const float* __restrict__ xz, const float* __restrict__ Dssm)
{
    int idx = blockIdx.x * 256 + threadIdx.x;   // over Mrows*DI
    int r = idx >> 10, j = idx & 1023;
    float z  = xz[(size_t)r * (2*DI) + DI + j];
    float yv = y[idx] + uact[idx] * Dssm[j];
    y[idx] = yv * (z / (1.f + expf(-z)));
}

// ---------------- fused residual-sum + LN1 + LN2 -----------------------------
__device__ __forceinline__ float blockSum128(float v, float* sm)
{
#pragma unroll
    for (int off = 16; off > 0; off >>= 1)
        v += __shfl_xor_sync(0xffffffffu, v, off);
    if ((threadIdx.x & 31) == 0) sm[threadIdx.x >> 5] = v;
    __syncthreads();
    float r = sm[0] + sm[1] + sm[2] + sm[3];
    __syncthreads();
    return r;
}

__global__ __launch_bounds__(128) void combine_ln_k(
    const float* __restrict__ xf, const float* __restrict__ attn,
    const float* __restrict__ mamba,
    const float* __restrict__ g1, const float* __restrict__ b1,
    const float* __restrict__ g2, const float* __restrict__ b2,
    float* __restrict__ h, float* __restrict__ hn)
{
    __shared__ float sm[4];
    int r = blockIdx.x, tid = threadIdx.x;
    size_t base = (size_t)r * Dd;
    float vv[4];
#pragma unroll
    for (int i = 0; i < 4; i++) {
        int c = tid + i*128;
        vv[i] = xf[base+c] + attn[base+c] + mamba[base+c];
    }
    float s = vv[0] + vv[1] + vv[2] + vv[3];
    float mean = blockSum128(s, sm) * (1.f/512.f);
    float sq = 0.f;
#pragma unroll
    for (int i = 0; i < 4; i++) { float dd = vv[i] - mean; sq = fmaf(dd, dd, sq); }
    float var = blockSum128(sq, sm) * (1.f/512.f);
    float inv = rsqrtf(var + 1e-5f);
    float hv[4];
#pragma unroll
    for (int i = 0; i < 4; i++) {
        int c = tid + i*128;
        hv[i] = (vv[i] - mean) * inv * g1[c] + b1[c];
        h[base+c] = hv[i];
    }
    float s2 = hv[0] + hv[1] + hv[2] + hv[3];
    float mean2 = blockSum128(s2, sm) * (1.f/512.f);
    float sq2 = 0.f;
#pragma unroll
    for (int i = 0; i < 4; i++) { float dd = hv[i] - mean2; sq2 = fmaf(dd, dd, sq2); }
    float var2 = blockSum128(sq2, sm) * (1.f/512.f);
    float inv2 = rsqrtf(var2 + 1e-6f);
#pragma unroll
    for (int i = 0; i < 4; i++) {
        int c = tid + i*128;
        hn[base+c] = (hv[i] - mean2) * inv2 * g2[c] + b2[c];
    }
}

// ---------------- launch -----------------------------------------------------
extern "C" void kernel_launch(void* const* d_in, const int* in_sizes, int n_in,
                              void* d_out, int out_size)
{
    const float* x          = (const float*)d_in[0];
    const unsigned char* mask = (const unsigned char*)d_in[1];
    const float* Wq = (const float*)d_in[2];   const float* bq = (const float*)d_in[3];
    const float* Wk = (const float*)d_in[4];   const float* bk = (const float*)d_in[5];
    const float* Wv = (const float*)d_in[6];   const float* bv = (const float*)d_in[7];
    const float* Wo = (const float*)d_in[8];   const float* bo = (const float*)d_in[9];
    const float* in_proj_w = (const float*)d_in[10];
    const float* conv_w    = (const float*)d_in[11];
    const float* conv_b    = (const float*)d_in[12];
    const float* x_proj_w  = (const float*)d_in[13];
    const float* dt_proj_w = (const float*)d_in[14];
    const float* dt_proj_b = (const float*)d_in[15];
    const float* A_log     = (const float*)d_in[16];
    const float* D_ssm     = (const float*)d_in[17];
    const float* out_proj_w= (const float*)d_in[18];
    const float* ln1_g = (const float*)d_in[19]; const float* ln1_b = (const float*)d_in[20];
    const float* ffn_w1= (const float*)d_in[21]; const float* ffn_b1= (const float*)d_in[22];
    const float* ffn_w2= (const float*)d_in[23]; const float* ffn_b2= (const float*)d_in[24];
    const float* ln2_g = (const float*)d_in[25]; const float* ln2_b = (const float*)d_in[26];
    float* out = (float*)d_out;

    float *q,*k,*v,*attnO,*attn_out,*xz,*uact,*xdbc,*delta,*y,*mamba,*h,*hn,*mid;
    cudaGetSymbolAddress((void**)&q,        g_q);
    cudaGetSymbolAddress((void**)&k,        g_k);
    cudaGetSymbolAddress((void**)&v,        g_v);
    cudaGetSymbolAddress((void**)&attnO,    g_attnO);
    cudaGetSymbolAddress((void**)&attn_out, g_attn_out);
    cudaGetSymbolAddress((void**)&xz,       g_xz);
    cudaGetSymbolAddress((void**)&uact,     g_uact);
    cudaGetSymbolAddress((void**)&xdbc,     g_xdbc);
    cudaGetSymbolAddress((void**)&delta,    g_delta);
    cudaGetSymbolAddress((void**)&y,        g_y);
    cudaGetSymbolAddress((void**)&mamba,    g_mamba);
    cudaGetSymbolAddress((void**)&h,        g_h);
    cudaGetSymbolAddress((void**)&hn,       g_hn);
    cudaGetSymbolAddress((void**)&mid,      g_mid);

    const int MY = Mrows / 128;   // 72

    // attention branch
    sgemm_k<EPI_NONE><<<dim3(Dd/64,   MY), 256>>>(x, Dd, Wq, bq, nullptr, q, Mrows, Dd, Dd);
    sgemm_k<EPI_NONE><<<dim3(Dd/64,   MY), 256>>>(x, Dd, Wk, bk, nullptr, k, Mrows, Dd, Dd);
    sgemm_k<EPI_NONE><<<dim3(Dd/64,   MY), 256>>>(x, Dd, Wv, bv, nullptr, v, Mrows, Dd, Dd);
    attn_k<<<dim3(LL/64, Hh, Bsz), 256>>>(q, k, v, mask, attnO);
    sgemm_k<EPI_NONE><<<dim3(Dd/64,   MY), 256>>>(attnO, Dd, Wo, bo, nullptr, attn_out, Mrows, Dd, Dd);

    // mamba branch
    sgemm_k<EPI_NONE><<<dim3(2*DI/64, MY), 256>>>(x, Dd, in_proj_w, nullptr, nullptr, xz, Mrows, 2*DI, Dd);
    conv_silu_k<<<Mrows*DI/256, 256>>>(xz, conv_w, conv_b, uact);
    sgemm_k<EPI_NONE><<<dim3(3,       MY), 256>>>(uact, DI, x_proj_w, nullptr, nullptr, xdbc, Mrows, 160, DI);
    sgemm_k<EPI_SOFTPLUS><<<dim3(DI/64, MY), 256>>>(xdbc, 160, dt_proj_w, dt_proj_b, nullptr, delta, Mrows, DI, Rr);
    scan_k<<<dim3(DI/16, Bsz), 512>>>(delta, uact, xdbc, A_log, y);
    gate_k<<<Mrows*DI/256, 256>>>(y, uact, xz, D_ssm);
    sgemm_k<EPI_NONE><<<dim3(Dd/64,   MY), 256>>>(y, DI, out_proj_w, nullptr, nullptr, mamba, Mrows, Dd, DI);

    // combine + double layernorm
    combine_ln_k<<<Mrows, 128>>>(x, attn_out, mamba, ln1_g, ln1_b, ln2_g, ln2_b, h, hn);

    // FFN
    sgemm_k<EPI_GELU><<<dim3(DFF/64, MY), 256>>>(hn, Dd, ffn_w1, ffn_b1, nullptr, mid, Mrows, DFF, Dd);
    sgemm_k<EPI_ADD><<<dim3(Dd/64,   MY), 256>>>(mid, DFF, ffn_w2, ffn_b2, h, out, Mrows, Dd, DFF);
}

// round 5
// speedup vs baseline: 1.8382x; 1.8382x over previous
#include <cuda_runtime.h>
#include <math.h>

#define Bsz 8
#define Dd 512
#define Hh 8
#define Ee 64
#define DI 1024
#define Ss 64
#define Rr 32
#define DFF 2048
#define LL 1152
#define Mrows (Bsz*LL)   /* 9216 */

// ---------------- scratch (static __device__, no allocation) ----------------
__device__ float g_q[Mrows*Dd];
__device__ float g_k[Mrows*Dd];
__device__ float g_v[Mrows*Dd];
__device__ float g_attnO[Mrows*Dd];
__device__ float g_attn_out[Mrows*Dd];
__device__ float g_xz[Mrows*2*DI];
__device__ float g_uact[Mrows*DI];
__device__ float g_xdbc[Mrows*160];
__device__ float g_delta[Mrows*DI];
__device__ float g_y[Mrows*DI];
__device__ float g_mamba[Mrows*Dd];
__device__ float g_h[Mrows*Dd];
__device__ float g_hn[Mrows*Dd];
__device__ float g_mid[Mrows*DFF];

enum { EPI_NONE = 0, EPI_SOFTPLUS = 1, EPI_GELU = 2, EPI_ADD = 3 };

// ================= tf32 tensor-core GEMM: C = A(MxK) @ W(NxK)^T ==============
// Block tile 128x64, BK=32, 8 warps (4x2), warp tile 32x32 via m16n8k8.
__device__ __forceinline__ unsigned f2tf32(float f)
{
    unsigned u;
    asm("cvt.rna.tf32.f32 %0, %1;" : "=r"(u) : "f"(f));
    return u;
}

__device__ __forceinline__ void mma_tf32(float* c, const unsigned* a, const unsigned* b)
{
    asm volatile(
        "mma.sync.aligned.m16n8k8.row.col.f32.tf32.tf32.f32 "
        "{%0,%1,%2,%3},{%4,%5,%6,%7},{%8,%9},{%0,%1,%2,%3};"
        : "+f"(c[0]), "+f"(c[1]), "+f"(c[2]), "+f"(c[3])
        : "r"(a[0]), "r"(a[1]), "r"(a[2]), "r"(a[3]), "r"(b[0]), "r"(b[1]));
}

template<int EPI>
__global__ __launch_bounds__(256) void gemm_tf32(
    const float* __restrict__ A, int lda,
    const float* __restrict__ W,
    const float* __restrict__ bias,
    const float* __restrict__ add,
    float* __restrict__ C, int M, int N, int K)
{
    // swizzled smem: elem(row, k) at row*32 + ((k/4 ^ (row&7))*4 + k%4)
    __shared__ __align__(16) unsigned As[2][128*32];
    __shared__ __align__(16) unsigned Bs[2][64*32];

    const int t = threadIdx.x;
    const int m0 = blockIdx.y * 128, n0 = blockIdx.x * 64;
    const int lane = t & 31, w = t >> 5;
    const int warpM = w & 3, warpN = w >> 2;
    const int s = lane >> 2, off = lane & 3;

    // -------- global->reg staging maps (A: 4 float4/thr, B: 2 float4/thr) ----
    const float* aptr[4]; int aso[4];
#pragma unroll
    for (int i = 0; i < 4; i++) {
        int e = t + i*256;
        int m = e >> 3, g = e & 7;
        aptr[i] = A + (size_t)(m0 + m) * lda + g*4;
        aso[i]  = m*32 + ((g ^ (m & 7)) << 2);
    }
    const float* bptr[2]; int bso[2]; bool bval[2];
#pragma unroll
    for (int i = 0; i < 2; i++) {
        int e = t + i*256;
        int n = e >> 3, g = e & 7;
        bval[i] = (n0 + n) < N;
        bptr[i] = W + (size_t)(n0 + n) * K + g*4;
        bso[i]  = n*32 + ((g ^ (n & 7)) << 2);
    }

    float acc[2][4][4];
#pragma unroll
    for (int mi = 0; mi < 2; mi++)
#pragma unroll
        for (int ni = 0; ni < 4; ni++)
#pragma unroll
            for (int j = 0; j < 4; j++) acc[mi][ni][j] = 0.f;

    const int nk = K >> 5;
    float4 ar[4], br[2];

    // prologue: tile 0
#pragma unroll
    for (int i = 0; i < 4; i++) ar[i] = *(const float4*)(aptr[i]);
#pragma unroll
    for (int i = 0; i < 2; i++)
        br[i] = bval[i] ? *(const float4*)(bptr[i]) : make_float4(0.f,0.f,0.f,0.f);
#pragma unroll
    for (int i = 0; i < 4; i++) {
        uint4 u = make_uint4(f2tf32(ar[i].x), f2tf32(ar[i].y), f2tf32(ar[i].z), f2tf32(ar[i].w));
        *(uint4*)&As[0][aso[i]] = u;
    }
#pragma unroll
    for (int i = 0; i < 2; i++) {
        uint4 u = make_uint4(f2tf32(br[i].x), f2tf32(br[i].y), f2tf32(br[i].z), f2tf32(br[i].w));
        *(uint4*)&Bs[0][bso[i]] = u;
    }
    __syncthreads();

    for (int kt = 0; kt < nk; kt++) {
        const int cur = kt & 1, nxt = cur ^ 1;
        const bool more = (kt + 1) < nk;
        if (more) {
            const int ko = (kt + 1) * 32;
#pragma unroll
            for (int i = 0; i < 4; i++) ar[i] = *(const float4*)(aptr[i] + ko);
#pragma unroll
            for (int i = 0; i < 2; i++)
                br[i] = bval[i] ? *(const float4*)(bptr[i] + ko) : make_float4(0.f,0.f,0.f,0.f);
        }

#pragma unroll
        for (int ks = 0; ks < 4; ks++) {
            const int x0 = (((ks*2)     ^ s) << 2) + off;
            const int x1 = (((ks*2 + 1) ^ s) << 2) + off;
            unsigned a[2][4];
#pragma unroll
            for (int mi = 0; mi < 2; mi++) {
                int r = (warpM*32 + mi*16 + s) * 32;
                a[mi][0] = As[cur][r + x0];
                a[mi][1] = As[cur][r + 256 + x0];
                a[mi][2] = As[cur][r + x1];
                a[mi][3] = As[cur][r + 256 + x1];
            }
            unsigned b[4][2];
#pragma unroll
            for (int ni = 0; ni < 4; ni++) {
                int rb = (warpN*32 + ni*8 + s) * 32;
                b[ni][0] = Bs[cur][rb + x0];
                b[ni][1] = Bs[cur][rb + x1];
            }
#pragma unroll
            for (int mi = 0; mi < 2; mi++)
#pragma unroll
                for (int ni = 0; ni < 4; ni++)
                    mma_tf32(acc[mi][ni], a[mi], b[ni]);
        }

        if (more) {
#pragma unroll
            for (int i = 0; i < 4; i++) {
                uint4 u = make_uint4(f2tf32(ar[i].x), f2tf32(ar[i].y), f2tf32(ar[i].z), f2tf32(ar[i].w));
                *(uint4*)&As[nxt][aso[i]] = u;
            }
#pragma unroll
            for (int i = 0; i < 2; i++) {
                uint4 u = make_uint4(f2tf32(br[i].x), f2tf32(br[i].y), f2tf32(br[i].z), f2tf32(br[i].w));
                *(uint4*)&Bs[nxt][bso[i]] = u;
            }
            __syncthreads();
        }
    }

    // -------- epilogue --------
#pragma unroll
    for (int mi = 0; mi < 2; mi++) {
#pragma unroll
        for (int ni = 0; ni < 4; ni++) {
            int row = m0 + warpM*32 + mi*16 + s;
            int col = n0 + warpN*32 + ni*8 + off*2;
            if (col < N) {
                float v00 = acc[mi][ni][0], v01 = acc[mi][ni][1];
                float v10 = acc[mi][ni][2], v11 = acc[mi][ni][3];
                if (bias) {
                    float b0 = bias[col], b1 = bias[col+1];
                    v00 += b0; v01 += b1; v10 += b0; v11 += b1;
                }
                if (EPI == EPI_SOFTPLUS) {
                    v00 = (v00 > 20.f) ? v00 : log1pf(expf(v00));
                    v01 = (v01 > 20.f) ? v01 : log1pf(expf(v01));
                    v10 = (v10 > 20.f) ? v10 : log1pf(expf(v10));
                    v11 = (v11 > 20.f) ? v11 : log1pf(expf(v11));
                } else if (EPI == EPI_GELU) {
                    v00 = 0.5f*v00*(1.f + erff(v00*0.7071067811865475f));
                    v01 = 0.5f*v01*(1.f + erff(v01*0.7071067811865475f));
                    v10 = 0.5f*v10*(1.f + erff(v10*0.7071067811865475f));
                    v11 = 0.5f*v11*(1.f + erff(v11*0.7071067811865475f));
                } else if (EPI == EPI_ADD) {
                    const float* ap0 = add + (size_t)row * N + col;
                    const float* ap1 = add + (size_t)(row+8) * N + col;
                    v00 += ap0[0]; v01 += ap0[1]; v10 += ap1[0]; v11 += ap1[1];
                }
                *(float2*)&C[(size_t)row * N + col]     = make_float2(v00, v01);
                *(float2*)&C[(size_t)(row+8) * N + col] = make_float2(v10, v11);
            }
        }
    }
}

// ---------------- flash attention: 64-row Q tile, 32-key tiles ---------------
__global__ __launch_bounds__(256) void attn_k(
    const float* __restrict__ q, const float* __restrict__ k,
    const float* __restrict__ v, const unsigned char* __restrict__ mask,
    float* __restrict__ o)
{
    __shared__ float QsT[64][64];
    __shared__ float KsT[64][32];
    __shared__ float Vs [32][64];
    __shared__ float PsT[32][68];

    int qt = blockIdx.x, h = blockIdx.y, b = blockIdx.z;
    int tid = threadIdx.x;
    int tx = tid & 15, ty = tid >> 4;
    const size_t bL = (size_t)b * LL;
    int q0 = qt * 64;

    for (int i = tid; i < 1024; i += 256) {
        int m = i >> 4, e4 = (i & 15) * 4;
        float4 qv = *(const float4*)&q[(bL + q0 + m) * Dd + h*Ee + e4];
        QsT[e4+0][m] = qv.x; QsT[e4+1][m] = qv.y;
        QsT[e4+2][m] = qv.z; QsT[e4+3][m] = qv.w;
    }

    float acc[4][4];
#pragma unroll
    for (int i = 0; i < 4; i++)
#pragma unroll
        for (int j = 0; j < 4; j++) acc[i][j] = 0.f;
    float mrow[4] = {-INFINITY, -INFINITY, -INFINITY, -INFINITY};
    float lrow[4] = {0.f, 0.f, 0.f, 0.f};
    const float scale = 0.125f;

    for (int n0k = 0; n0k < LL; n0k += 32) {
        __syncthreads();
        for (int i = tid; i < 512; i += 256) {
            int n = i >> 4, e4 = (i & 15) * 4;
            size_t gr = (bL + n0k + n) * Dd + h*Ee + e4;
            float4 kv = *(const float4*)&k[gr];
            KsT[e4+0][n] = kv.x; KsT[e4+1][n] = kv.y;
            KsT[e4+2][n] = kv.z; KsT[e4+3][n] = kv.w;
            float4 vv = *(const float4*)&v[gr];
            *(float4*)&Vs[n][e4] = vv;
        }
        __syncthreads();

        float s[4][2];
#pragma unroll
        for (int i = 0; i < 4; i++) { s[i][0] = 0.f; s[i][1] = 0.f; }
#pragma unroll 16
        for (int e = 0; e < 64; e++) {
            float4 qv = *(const float4*)&QsT[e][ty*4];
            float2 kv = *(const float2*)&KsT[e][tx*2];
            s[0][0] = fmaf(qv.x, kv.x, s[0][0]); s[0][1] = fmaf(qv.x, kv.y, s[0][1]);
            s[1][0] = fmaf(qv.y, kv.x, s[1][0]); s[1][1] = fmaf(qv.y, kv.y, s[1][1]);
            s[2][0] = fmaf(qv.z, kv.x, s[2][0]); s[2][1] = fmaf(qv.z, kv.y, s[2][1]);
            s[3][0] = fmaf(qv.w, kv.x, s[3][0]); s[3][1] = fmaf(qv.w, kv.y, s[3][1]);
        }

        unsigned char mk0 = mask[bL + n0k + tx*2 + 0];
        unsigned char mk1 = mask[bL + n0k + tx*2 + 1];
        float p[4][2];
#pragma unroll
        for (int i = 0; i < 4; i++) {
            float s0 = s[i][0] * scale, s1 = s[i][1] * scale;
            if (mk0) s0 = -INFINITY;
            if (mk1) s1 = -INFINITY;
            float tmx = fmaxf(s0, s1);
#pragma unroll
            for (int offx = 1; offx < 16; offx <<= 1)
                tmx = fmaxf(tmx, __shfl_xor_sync(0xffffffffu, tmx, offx));
            float mnew = fmaxf(mrow[i], tmx);
            float p0 = __expf(s0 - mnew), p1 = __expf(s1 - mnew);
            float rs = p0 + p1;
#pragma unroll
            for (int offx = 1; offx < 16; offx <<= 1)
                rs += __shfl_xor_sync(0xffffffffu, rs, offx);
            float corr = __expf(mrow[i] - mnew);
            lrow[i] = lrow[i] * corr + rs;
            mrow[i] = mnew;
            acc[i][0] *= corr; acc[i][1] *= corr;
            acc[i][2] *= corr; acc[i][3] *= corr;
            p[i][0] = p0; p[i][1] = p1;
        }
#pragma unroll
        for (int j = 0; j < 2; j++) {
            int n = tx*2 + j;
            *(float4*)&PsT[n][ty*4] = make_float4(p[0][j], p[1][j], p[2][j], p[3][j]);
        }
        __syncthreads();
#pragma unroll 8
        for (int n = 0; n < 32; n++) {
            float4 pv = *(const float4*)&PsT[n][ty*4];
            float4 vv = *(const float4*)&Vs[n][tx*4];
            acc[0][0] = fmaf(pv.x, vv.x, acc[0][0]); acc[0][1] = fmaf(pv.x, vv.y, acc[0][1]);
            acc[0][2] = fmaf(pv.x, vv.z, acc[0][2]); acc[0][3] = fmaf(pv.x, vv.w, acc[0][3]);
            acc[1][0] = fmaf(pv.y, vv.x, acc[1][0]); acc[1][1] = fmaf(pv.y, vv.y, acc[1][1]);
            acc[1][2] = fmaf(pv.y, vv.z, acc[1][2]); acc[1][3] = fmaf(pv.y, vv.w, acc[1][3]);
            acc[2][0] = fmaf(pv.z, vv.x, acc[2][0]); acc[2][1] = fmaf(pv.z, vv.y, acc[2][1]);
            acc[2][2] = fmaf(pv.z, vv.z, acc[2][2]); acc[2][3] = fmaf(pv.z, vv.w, acc[2][3]);
            acc[3][0] = fmaf(pv.w, vv.x, acc[3][0]); acc[3][1] = fmaf(pv.w, vv.y, acc[3][1]);
            acc[3][2] = fmaf(pv.w, vv.z, acc[3][2]); acc[3][3] = fmaf(pv.w, vv.w, acc[3][3]);
        }
    }

#pragma unroll
    for (int i = 0; i < 4; i++) {
        float inv = 1.f / lrow[i];
        size_t row = (bL + q0 + ty*4 + i) * Dd + h*Ee + tx*4;
        *(float4*)&o[row] = make_float4(acc[i][0]*inv, acc[i][1]*inv,
                                        acc[i][2]*inv, acc[i][3]*inv);
    }
}

// ---------------- causal depthwise conv (KC=4) + SiLU ------------------------
__global__ void conv_silu_k(const float* __restrict__ xz,
                            const float* __restrict__ cw,
                            const float* __restrict__ cb,
                            float* __restrict__ uact)
{
    int idx = blockIdx.x * 256 + threadIdx.x;
    int r = idx >> 10;
    int j = idx & 1023;
    int t = r % LL;
    float acc = cb[j];
#pragma unroll
    for (int kk = 0; kk < 4; kk++) {
        int tt = t + kk - 3;
        if (tt >= 0)
            acc = fmaf(xz[(size_t)(r + kk - 3) * (2*DI) + j], cw[j*4 + kk], acc);
    }
    uact[idx] = acc / (1.f + expf(-acc));
}

// ---------------- selective scan: 1 warp per (b,d), 2 states/lane ------------
__global__ __launch_bounds__(512) void scan_k(
    const float* __restrict__ delta, const float* __restrict__ uact,
    const float* __restrict__ xdbc, const float* __restrict__ A_log,
    float* __restrict__ y)
{
    __shared__ float sB[16][64];
    __shared__ float sC[16][64];
    __shared__ float sdt[16][16];
    __shared__ float su[16][16];

    int b = blockIdx.y;
    int d0 = blockIdx.x * 16;
    int tid = threadIdx.x;
    int w = tid >> 5, l = tid & 31;
    int d = d0 + w;
    float a0 = -expf(A_log[d*Ss + l]);
    float a1 = -expf(A_log[d*Ss + l + 32]);
    float h0 = 0.f, h1 = 0.f;
    size_t base = (size_t)b * LL;

    for (int t0 = 0; t0 < LL; t0 += 16) {
        __syncthreads();
        for (int i = tid; i < 2048; i += 512) {
            int tt = i >> 7, c = i & 127;
            float val = xdbc[(base + t0 + tt) * 160 + 32 + c];
            if (c < 64) sB[tt][c] = val; else sC[tt][c - 64] = val;
        }
        if (tid < 256) {
            sdt[tid >> 4][tid & 15] = delta[(base + t0 + (tid >> 4)) * DI + d0 + (tid & 15)];
        } else {
            int jj = tid - 256;
            su[jj >> 4][jj & 15] = uact[(base + t0 + (jj >> 4)) * DI + d0 + (jj & 15)];
        }
        __syncthreads();
#pragma unroll 4
        for (int tt = 0; tt < 16; tt++) {
            float dt  = sdt[tt][w];
            float dtu = dt * su[tt][w];
            float dA0 = __expf(dt * a0);
            float dA1 = __expf(dt * a1);
            h0 = fmaf(h0, dA0, dtu * sB[tt][l]);
            h1 = fmaf(h1, dA1, dtu * sB[tt][l + 32]);
            float yv = h0 * sC[tt][l] + h1 * sC[tt][l + 32];
#pragma unroll
            for (int offx = 16; offx > 0; offx >>= 1)
                yv += __shfl_xor_sync(0xffffffffu, yv, offx);
            if (l == 0) y[(base + t0 + tt) * DI + d] = yv;
        }
    }
}

// ---------------- gate: y = (y + uact*D) * silu(z) ---------------------------
__global__ void gate_k(float* __restrict__ y, const float* __restrict__ uact,
                       const float* __restrict__ xz, const float* __restrict__ Dssm)
{
    int idx = blockIdx.x * 256 + threadIdx.x;
    int r = idx >> 10, j = idx & 1023;
    float z  = xz[(size_t)r * (2*DI) + DI + j];
    float yv = y[idx] + uact[idx] * Dssm[j];
    y[idx] = yv * (z / (1.f + expf(-z)));
}

// ---------------- fused residual-sum + LN1 + LN2 -----------------------------
__device__ __forceinline__ float blockSum128(float v, float* sm)
{
#pragma unroll
    for (int offx = 16; offx > 0; offx >>= 1)
        v += __shfl_xor_sync(0xffffffffu, v, offx);
    if ((threadIdx.x & 31) == 0) sm[threadIdx.x >> 5] = v;
    __syncthreads();
    float r = sm[0] + sm[1] + sm[2] + sm[3];
    __syncthreads();
    return r;
}

__global__ __launch_bounds__(128) void combine_ln_k(
    const float* __restrict__ xf, const float* __restrict__ attn,
    const float* __restrict__ mamba,
    const float* __restrict__ g1, const float* __restrict__ b1,
    const float* __restrict__ g2, const float* __restrict__ b2,
    float* __restrict__ h, float* __restrict__ hn)
{
    __shared__ float sm[4];
    int r = blockIdx.x, tid = threadIdx.x;
    size_t base = (size_t)r * Dd;
    float vv[4];
#pragma unroll
    for (int i = 0; i < 4; i++) {
        int c = tid + i*128;
        vv[i] = xf[base+c] + attn[base+c] + mamba[base+c];
    }
    float s = vv[0] + vv[1] + vv[2] + vv[3];
    float mean = blockSum128(s, sm) * (1.f/512.f);
    float sq = 0.f;
#pragma unroll
    for (int i = 0; i < 4; i++) { float dd = vv[i] - mean; sq = fmaf(dd, dd, sq); }
    float var = blockSum128(sq, sm) * (1.f/512.f);
    float inv = rsqrtf(var + 1e-5f);
    float hv[4];
#pragma unroll
    for (int i = 0; i < 4; i++) {
        int c = tid + i*128;
        hv[i] = (vv[i] - mean) * inv * g1[c] + b1[c];
        h[base+c] = hv[i];
    }
    float s2 = hv[0] + hv[1] + hv[2] + hv[3];
    float mean2 = blockSum128(s2, sm) * (1.f/512.f);
    float sq2 = 0.f;
#pragma unroll
    for (int i = 0; i < 4; i++) { float dd = hv[i] - mean2; sq2 = fmaf(dd, dd, sq2); }
    float var2 = blockSum128(sq2, sm) * (1.f/512.f);
    float inv2 = rsqrtf(var2 + 1e-6f);
#pragma unroll
    for (int i = 0; i < 4; i++) {
        int c = tid + i*128;
        hn[base+c] = (hv[i] - mean2) * inv2 * g2[c] + b2[c];
    }
}

// ---------------- launch -----------------------------------------------------
extern "C" void kernel_launch(void* const* d_in, const int* in_sizes, int n_in,
                              void* d_out, int out_size)
{
    const float* x            = (const float*)d_in[0];
    const unsigned char* mask = (const unsigned char*)d_in[1];
    const float* Wq = (const float*)d_in[2];   const float* bq = (const float*)d_in[3];
    const float* Wk = (const float*)d_in[4];   const float* bk = (const float*)d_in[5];
    const float* Wv = (const float*)d_in[6];   const float* bv = (const float*)d_in[7];
    const float* Wo = (const float*)d_in[8];   const float* bo = (const float*)d_in[9];
    const float* in_proj_w = (const float*)d_in[10];
    const float* conv_w    = (const float*)d_in[11];
    const float* conv_b    = (const float*)d_in[12];
    const float* x_proj_w  = (const float*)d_in[13];
    const float* dt_proj_w = (const float*)d_in[14];
    const float* dt_proj_b = (const float*)d_in[15];
    const float* A_log     = (const float*)d_in[16];
    const float* D_ssm     = (const float*)d_in[17];
    const float* out_proj_w= (const float*)d_in[18];
    const float* ln1_g = (const float*)d_in[19]; const float* ln1_b = (const float*)d_in[20];
    const float* ffn_w1= (const float*)d_in[21]; const float* ffn_b1= (const float*)d_in[22];
    const float* ffn_w2= (const float*)d_in[23]; const float* ffn_b2= (const float*)d_in[24];
    const float* ln2_g = (const float*)d_in[25]; const float* ln2_b = (const float*)d_in[26];
    float* out = (float*)d_out;

    float *q,*k,*v,*attnO,*attn_out,*xz,*uact,*xdbc,*delta,*y,*mamba,*h,*hn,*mid;
    cudaGetSymbolAddress((void**)&q,        g_q);
    cudaGetSymbolAddress((void**)&k,        g_k);
    cudaGetSymbolAddress((void**)&v,        g_v);
    cudaGetSymbolAddress((void**)&attnO,    g_attnO);
    cudaGetSymbolAddress((void**)&attn_out, g_attn_out);
    cudaGetSymbolAddress((void**)&xz,       g_xz);
    cudaGetSymbolAddress((void**)&uact,     g_uact);
    cudaGetSymbolAddress((void**)&xdbc,     g_xdbc);
    cudaGetSymbolAddress((void**)&delta,    g_delta);
    cudaGetSymbolAddress((void**)&y,        g_y);
    cudaGetSymbolAddress((void**)&mamba,    g_mamba);
    cudaGetSymbolAddress((void**)&h,        g_h);
    cudaGetSymbolAddress((void**)&hn,       g_hn);
    cudaGetSymbolAddress((void**)&mid,      g_mid);

    const int MY = Mrows / 128;   // 72

    // attention branch
    gemm_tf32<EPI_NONE><<<dim3(Dd/64,   MY), 256>>>(x, Dd, Wq, bq, nullptr, q, Mrows, Dd, Dd);
    gemm_tf32<EPI_NONE><<<dim3(Dd/64,   MY), 256>>>(x, Dd, Wk, bk, nullptr, k, Mrows, Dd, Dd);
    gemm_tf32<EPI_NONE><<<dim3(Dd/64,   MY), 256>>>(x, Dd, Wv, bv, nullptr, v, Mrows, Dd, Dd);
    attn_k<<<dim3(LL/64, Hh, Bsz), 256>>>(q, k, v, mask, attnO);
    gemm_tf32<EPI_NONE><<<dim3(Dd/64,   MY), 256>>>(attnO, Dd, Wo, bo, nullptr, attn_out, Mrows, Dd, Dd);

    // mamba branch
    gemm_tf32<EPI_NONE><<<dim3(2*DI/64, MY), 256>>>(x, Dd, in_proj_w, nullptr, nullptr, xz, Mrows, 2*DI, Dd);
    conv_silu_k<<<Mrows*DI/256, 256>>>(xz, conv_w, conv_b, uact);
    gemm_tf32<EPI_NONE><<<dim3(3,       MY), 256>>>(uact, DI, x_proj_w, nullptr, nullptr, xdbc, Mrows, 160, DI);
    gemm_tf32<EPI_SOFTPLUS><<<dim3(DI/64, MY), 256>>>(xdbc, 160, dt_proj_w, dt_proj_b, nullptr, delta, Mrows, DI, Rr);
    scan_k<<<dim3(DI/16, Bsz), 512>>>(delta, uact, xdbc, A_log, y);
    gate_k<<<Mrows*DI/256, 256>>>(y, uact, xz, D_ssm);
    gemm_tf32<EPI_NONE><<<dim3(Dd/64,   MY), 256>>>(y, DI, out_proj_w, nullptr, nullptr, mamba, Mrows, Dd, DI);

    // combine + double layernorm
    combine_ln_k<<<Mrows, 128>>>(x, attn_out, mamba, ln1_g, ln1_b, ln2_g, ln2_b, h, hn);

    // FFN
    gemm_tf32<EPI_GELU><<<dim3(DFF/64, MY), 256>>>(hn, Dd, ffn_w1, ffn_b1, nullptr, mid, Mrows, DFF, Dd);
    gemm_tf32<EPI_ADD><<<dim3(Dd/64,   MY), 256>>>(mid, DFF, ffn_w2, ffn_b2, h, out, Mrows, Dd, DFF);
}

// round 6
// speedup vs baseline: 2.3986x; 1.3049x over previous
#include <cuda_runtime.h>
#include <math.h>

#define Bsz 8
#define Dd 512
#define Hh 8
#define Ee 64
#define DI 1024
#define Ss 64
#define Rr 32
#define DFF 2048
#define LL 1152
#define Mrows (Bsz*LL)   /* 9216 */

// ---------------- scratch (static __device__, no allocation) ----------------
__device__ float g_q[Mrows*Dd];
__device__ float g_k[Mrows*Dd];
__device__ float g_v[Mrows*Dd];
__device__ float g_attnO[Mrows*Dd];
__device__ float g_attn_out[Mrows*Dd];
__device__ float g_xz[Mrows*2*DI];
__device__ float g_uact[Mrows*DI];
__device__ float g_xdbc[Mrows*160];
__device__ float g_delta[Mrows*DI];
__device__ float g_y[Mrows*DI];
__device__ float g_mamba[Mrows*Dd];
__device__ float g_h[Mrows*Dd];
__device__ float g_hn[Mrows*Dd];
__device__ float g_mid[Mrows*DFF];

enum { EPI_NONE = 0, EPI_SOFTPLUS = 1, EPI_GELU = 2, EPI_ADD = 3 };

__device__ __forceinline__ unsigned f2tf32(float f)
{
    unsigned u;
    asm("cvt.rna.tf32.f32 %0, %1;" : "=r"(u) : "f"(f));
    return u;
}

__device__ __forceinline__ void mma_tf32(float* c, const unsigned* a, const unsigned* b)
{
    asm volatile(
        "mma.sync.aligned.m16n8k8.row.col.f32.tf32.tf32.f32 "
        "{%0,%1,%2,%3},{%4,%5,%6,%7},{%8,%9},{%0,%1,%2,%3};"
        : "+f"(c[0]), "+f"(c[1]), "+f"(c[2]), "+f"(c[3])
        : "r"(a[0]), "r"(a[1]), "r"(a[2]), "r"(a[3]), "r"(b[0]), "r"(b[1]));
}

// ================= tf32 tensor-core GEMM: C = A(MxK) @ W(NxK)^T ==============
template<int EPI>
__global__ __launch_bounds__(256) void gemm_tf32(
    const float* __restrict__ A, int lda,
    const float* __restrict__ W,
    const float* __restrict__ bias,
    const float* __restrict__ add,
    float* __restrict__ C, int M, int N, int K)
{
    __shared__ __align__(16) unsigned As[2][128*32];
    __shared__ __align__(16) unsigned Bs[2][64*32];

    const int t = threadIdx.x;
    const int m0 = blockIdx.y * 128, n0 = blockIdx.x * 64;
    const int lane = t & 31, w = t >> 5;
    const int warpM = w & 3, warpN = w >> 2;
    const int s = lane >> 2, off = lane & 3;

    const float* aptr[4]; int aso[4];
#pragma unroll
    for (int i = 0; i < 4; i++) {
        int e = t + i*256;
        int m = e >> 3, g = e & 7;
        aptr[i] = A + (size_t)(m0 + m) * lda + g*4;
        aso[i]  = m*32 + ((g ^ (m & 7)) << 2);
    }
    const float* bptr[2]; int bso[2]; bool bval[2];
#pragma unroll
    for (int i = 0; i < 2; i++) {
        int e = t + i*256;
        int n = e >> 3, g = e & 7;
        bval[i] = (n0 + n) < N;
        bptr[i] = W + (size_t)(n0 + n) * K + g*4;
        bso[i]  = n*32 + ((g ^ (n & 7)) << 2);
    }

    float acc[2][4][4];
#pragma unroll
    for (int mi = 0; mi < 2; mi++)
#pragma unroll
        for (int ni = 0; ni < 4; ni++)
#pragma unroll
            for (int j = 0; j < 4; j++) acc[mi][ni][j] = 0.f;

    const int nk = K >> 5;
    float4 ar[4], br[2];

#pragma unroll
    for (int i = 0; i < 4; i++) ar[i] = *(const float4*)(aptr[i]);
#pragma unroll
    for (int i = 0; i < 2; i++)
        br[i] = bval[i] ? *(const float4*)(bptr[i]) : make_float4(0.f,0.f,0.f,0.f);
#pragma unroll
    for (int i = 0; i < 4; i++)
        *(uint4*)&As[0][aso[i]] = make_uint4(f2tf32(ar[i].x), f2tf32(ar[i].y), f2tf32(ar[i].z), f2tf32(ar[i].w));
#pragma unroll
    for (int i = 0; i < 2; i++)
        *(uint4*)&Bs[0][bso[i]] = make_uint4(f2tf32(br[i].x), f2tf32(br[i].y), f2tf32(br[i].z), f2tf32(br[i].w));
    __syncthreads();

    for (int kt = 0; kt < nk; kt++) {
        const int cur = kt & 1, nxt = cur ^ 1;
        const bool more = (kt + 1) < nk;
        if (more) {
            const int ko = (kt + 1) * 32;
#pragma unroll
            for (int i = 0; i < 4; i++) ar[i] = *(const float4*)(aptr[i] + ko);
#pragma unroll
            for (int i = 0; i < 2; i++)
                br[i] = bval[i] ? *(const float4*)(bptr[i] + ko) : make_float4(0.f,0.f,0.f,0.f);
        }

#pragma unroll
        for (int ks = 0; ks < 4; ks++) {
            const int x0 = (((ks*2)     ^ s) << 2) + off;
            const int x1 = (((ks*2 + 1) ^ s) << 2) + off;
            unsigned a[2][4];
#pragma unroll
            for (int mi = 0; mi < 2; mi++) {
                int r = (warpM*32 + mi*16 + s) * 32;
                a[mi][0] = As[cur][r + x0];
                a[mi][1] = As[cur][r + 256 + x0];
                a[mi][2] = As[cur][r + x1];
                a[mi][3] = As[cur][r + 256 + x1];
            }
            unsigned b[4][2];
#pragma unroll
            for (int ni = 0; ni < 4; ni++) {
                int rb = (warpN*32 + ni*8 + s) * 32;
                b[ni][0] = Bs[cur][rb + x0];
                b[ni][1] = Bs[cur][rb + x1];
            }
#pragma unroll
            for (int mi = 0; mi < 2; mi++)
#pragma unroll
                for (int ni = 0; ni < 4; ni++)
                    mma_tf32(acc[mi][ni], a[mi], b[ni]);
        }

        if (more) {
#pragma unroll
            for (int i = 0; i < 4; i++)
                *(uint4*)&As[nxt][aso[i]] = make_uint4(f2tf32(ar[i].x), f2tf32(ar[i].y), f2tf32(ar[i].z), f2tf32(ar[i].w));
#pragma unroll
            for (int i = 0; i < 2; i++)
                *(uint4*)&Bs[nxt][bso[i]] = make_uint4(f2tf32(br[i].x), f2tf32(br[i].y), f2tf32(br[i].z), f2tf32(br[i].w));
            __syncthreads();
        }
    }

#pragma unroll
    for (int mi = 0; mi < 2; mi++) {
#pragma unroll
        for (int ni = 0; ni < 4; ni++) {
            int row = m0 + warpM*32 + mi*16 + s;
            int col = n0 + warpN*32 + ni*8 + off*2;
            if (col < N) {
                float v00 = acc[mi][ni][0], v01 = acc[mi][ni][1];
                float v10 = acc[mi][ni][2], v11 = acc[mi][ni][3];
                if (bias) {
                    float b0 = bias[col], b1 = bias[col+1];
                    v00 += b0; v01 += b1; v10 += b0; v11 += b1;
                }
                if (EPI == EPI_SOFTPLUS) {
                    v00 = (v00 > 20.f) ? v00 : log1pf(expf(v00));
                    v01 = (v01 > 20.f) ? v01 : log1pf(expf(v01));
                    v10 = (v10 > 20.f) ? v10 : log1pf(expf(v10));
                    v11 = (v11 > 20.f) ? v11 : log1pf(expf(v11));
                } else if (EPI == EPI_GELU) {
                    v00 = 0.5f*v00*(1.f + erff(v00*0.7071067811865475f));
                    v01 = 0.5f*v01*(1.f + erff(v01*0.7071067811865475f));
                    v10 = 0.5f*v10*(1.f + erff(v10*0.7071067811865475f));
                    v11 = 0.5f*v11*(1.f + erff(v11*0.7071067811865475f));
                } else if (EPI == EPI_ADD) {
                    const float* ap0 = add + (size_t)row * N + col;
                    const float* ap1 = add + (size_t)(row+8) * N + col;
                    v00 += ap0[0]; v01 += ap0[1]; v10 += ap1[0]; v11 += ap1[1];
                }
                *(float2*)&C[(size_t)row * N + col]     = make_float2(v00, v01);
                *(float2*)&C[(size_t)(row+8) * N + col] = make_float2(v10, v11);
            }
        }
    }
}

// ============== tf32 tensor-core flash attention =============================
// Block: 128 query rows x (b,h). 8 warps, 16 rows/warp. 64-key tiles.
// SMEM (dynamic): Ks[64][68] + Vs[64][68] + per-warp P[16][68]  (tf32 words)
__global__ __launch_bounds__(256) void attn_tc(
    const float* __restrict__ q, const float* __restrict__ k,
    const float* __restrict__ v, const unsigned char* __restrict__ mask,
    float* __restrict__ o)
{
    extern __shared__ unsigned sm_u[];
    unsigned* Ks = sm_u;                 // [64][68]
    unsigned* Vs = sm_u + 64*68;         // [64][68]
    const int tid = threadIdx.x;
    const int lane = tid & 31, w = tid >> 5;
    unsigned* Ps = sm_u + 2*64*68 + w*16*68;   // per-warp [16][68]
    const int s = lane >> 2, off = lane & 3;

    const int qt = blockIdx.x, h = blockIdx.y, b = blockIdx.z;
    const size_t bL = (size_t)b * LL;
    const int qr = qt * 128 + w * 16;

    // Q fragments, pre-scaled by 1/8 (exact power-of-two, no precision loss)
    unsigned qa[8][4];
    {
        const float* qp = q + (bL + qr) * Dd + h * Ee;
#pragma unroll
        for (int ks = 0; ks < 8; ks++) {
            qa[ks][0] = f2tf32(0.125f * qp[(size_t)(s    ) * Dd + ks*8 + off    ]);
            qa[ks][1] = f2tf32(0.125f * qp[(size_t)(s + 8) * Dd + ks*8 + off    ]);
            qa[ks][2] = f2tf32(0.125f * qp[(size_t)(s    ) * Dd + ks*8 + off + 4]);
            qa[ks][3] = f2tf32(0.125f * qp[(size_t)(s + 8) * Dd + ks*8 + off + 4]);
        }
    }

    float oa[8][4];
#pragma unroll
    for (int et = 0; et < 8; et++)
#pragma unroll
        for (int j = 0; j < 4; j++) oa[et][j] = 0.f;
    float m0v = -INFINITY, m1v = -INFINITY, l0v = 0.f, l1v = 0.f;

    for (int n0k = 0; n0k < LL; n0k += 64) {
        __syncthreads();
        // stage K/V tile (tf32 words, row pad 68)
#pragma unroll
        for (int i = 0; i < 4; i++) {
            int u = tid + i*256;
            int row = u >> 4, qc = (u & 15) * 4;
            size_t gr = (bL + n0k + row) * Dd + h*Ee + qc;
            float4 kv = *(const float4*)&k[gr];
            *(uint4*)&Ks[row*68 + qc] = make_uint4(f2tf32(kv.x), f2tf32(kv.y), f2tf32(kv.z), f2tf32(kv.w));
            float4 vv = *(const float4*)&v[gr];
            *(uint4*)&Vs[row*68 + qc] = make_uint4(f2tf32(vv.x), f2tf32(vv.y), f2tf32(vv.z), f2tf32(vv.w));
        }
        __syncthreads();

        // S = (Q/8) K^T  : sa[nt] covers keys nt*8..nt*8+7
        float sa[8][4];
#pragma unroll
        for (int nt = 0; nt < 8; nt++)
#pragma unroll
            for (int j = 0; j < 4; j++) sa[nt][j] = 0.f;
#pragma unroll
        for (int ks = 0; ks < 8; ks++) {
#pragma unroll
            for (int nt = 0; nt < 8; nt++) {
                unsigned bf[2];
                bf[0] = Ks[(nt*8 + s)*68 + ks*8 + off];
                bf[1] = Ks[(nt*8 + s)*68 + ks*8 + off + 4];
                mma_tf32(sa[nt], qa[ks], bf);
            }
        }

        // mask + online softmax (rows s and s+8; 4 threads per row -> quad shfl)
        float rmax0 = -INFINITY, rmax1 = -INFINITY;
#pragma unroll
        for (int nt = 0; nt < 8; nt++) {
            unsigned char mk0 = mask[bL + n0k + nt*8 + off*2];
            unsigned char mk1 = mask[bL + n0k + nt*8 + off*2 + 1];
            if (mk0) { sa[nt][0] = -INFINITY; sa[nt][2] = -INFINITY; }
            if (mk1) { sa[nt][1] = -INFINITY; sa[nt][3] = -INFINITY; }
            rmax0 = fmaxf(rmax0, fmaxf(sa[nt][0], sa[nt][1]));
            rmax1 = fmaxf(rmax1, fmaxf(sa[nt][2], sa[nt][3]));
        }
        rmax0 = fmaxf(rmax0, __shfl_xor_sync(0xffffffffu, rmax0, 1));
        rmax0 = fmaxf(rmax0, __shfl_xor_sync(0xffffffffu, rmax0, 2));
        rmax1 = fmaxf(rmax1, __shfl_xor_sync(0xffffffffu, rmax1, 1));
        rmax1 = fmaxf(rmax1, __shfl_xor_sync(0xffffffffu, rmax1, 2));
        float mn0 = fmaxf(m0v, rmax0), mn1 = fmaxf(m1v, rmax1);
        float c0 = __expf(m0v - mn0), c1 = __expf(m1v - mn1);
        float rs0 = 0.f, rs1 = 0.f;
#pragma unroll
        for (int nt = 0; nt < 8; nt++) {
            float p0 = __expf(sa[nt][0] - mn0);
            float p1 = __expf(sa[nt][1] - mn0);
            float p2 = __expf(sa[nt][2] - mn1);
            float p3 = __expf(sa[nt][3] - mn1);
            rs0 += p0 + p1; rs1 += p2 + p3;
            Ps[ s     *68 + nt*8 + off*2    ] = f2tf32(p0);
            Ps[ s     *68 + nt*8 + off*2 + 1] = f2tf32(p1);
            Ps[(s + 8)*68 + nt*8 + off*2    ] = f2tf32(p2);
            Ps[(s + 8)*68 + nt*8 + off*2 + 1] = f2tf32(p3);
        }
        rs0 += __shfl_xor_sync(0xffffffffu, rs0, 1);
        rs0 += __shfl_xor_sync(0xffffffffu, rs0, 2);
        rs1 += __shfl_xor_sync(0xffffffffu, rs1, 1);
        rs1 += __shfl_xor_sync(0xffffffffu, rs1, 2);
        l0v = l0v * c0 + rs0; l1v = l1v * c1 + rs1;
        m0v = mn0; m1v = mn1;
#pragma unroll
        for (int et = 0; et < 8; et++) {
            oa[et][0] *= c0; oa[et][1] *= c0;
            oa[et][2] *= c1; oa[et][3] *= c1;
        }
        __syncwarp();

        // O += P V
#pragma unroll
        for (int ks = 0; ks < 8; ks++) {
            unsigned pa[4];
            pa[0] = Ps[ s     *68 + ks*8 + off    ];
            pa[1] = Ps[(s + 8)*68 + ks*8 + off    ];
            pa[2] = Ps[ s     *68 + ks*8 + off + 4];
            pa[3] = Ps[(s + 8)*68 + ks*8 + off + 4];
#pragma unroll
            for (int et = 0; et < 8; et++) {
                unsigned bf[2];
                bf[0] = Vs[(ks*8 + off    )*68 + et*8 + s];
                bf[1] = Vs[(ks*8 + off + 4)*68 + et*8 + s];
                mma_tf32(oa[et], pa, bf);
            }
        }
    }

    float inv0 = 1.f / l0v, inv1 = 1.f / l1v;
#pragma unroll
    for (int et = 0; et < 8; et++) {
        size_t r0 = (bL + qr + s    ) * Dd + h*Ee + et*8 + off*2;
        size_t r1 = (bL + qr + s + 8) * Dd + h*Ee + et*8 + off*2;
        *(float2*)&o[r0] = make_float2(oa[et][0]*inv0, oa[et][1]*inv0);
        *(float2*)&o[r1] = make_float2(oa[et][2]*inv1, oa[et][3]*inv1);
    }
}

// ---------------- causal depthwise conv (KC=4) + SiLU ------------------------
__global__ void conv_silu_k(const float* __restrict__ xz,
                            const float* __restrict__ cw,
                            const float* __restrict__ cb,
                            float* __restrict__ uact)
{
    int idx = blockIdx.x * 256 + threadIdx.x;
    int r = idx >> 10;
    int j = idx & 1023;
    int t = r % LL;
    float acc = cb[j];
#pragma unroll
    for (int kk = 0; kk < 4; kk++) {
        int tt = t + kk - 3;
        if (tt >= 0)
            acc = fmaf(xz[(size_t)(r + kk - 3) * (2*DI) + j], cw[j*4 + kk], acc);
    }
    uact[idx] = acc / (1.f + expf(-acc));
}

// ---------------- selective scan: 1 warp per (b,d), 2 states/lane ------------
__global__ __launch_bounds__(512) void scan_k(
    const float* __restrict__ delta, const float* __restrict__ uact,
    const float* __restrict__ xdbc, const float* __restrict__ A_log,
    float* __restrict__ y)
{
    __shared__ float sB[16][64];
    __shared__ float sC[16][64];
    __shared__ float sdt[16][16];
    __shared__ float su[16][16];

    int b = blockIdx.y;
    int d0 = blockIdx.x * 16;
    int tid = threadIdx.x;
    int w = tid >> 5, l = tid & 31;
    int d = d0 + w;
    float a0 = -expf(A_log[d*Ss + l]);
    float a1 = -expf(A_log[d*Ss + l + 32]);
    float h0 = 0.f, h1 = 0.f;
    size_t base = (size_t)b * LL;

    for (int t0 = 0; t0 < LL; t0 += 16) {
        __syncthreads();
        for (int i = tid; i < 2048; i += 512) {
            int tt = i >> 7, c = i & 127;
            float val = xdbc[(base + t0 + tt) * 160 + 32 + c];
            if (c < 64) sB[tt][c] = val; else sC[tt][c - 64] = val;
        }
        if (tid < 256) {
            sdt[tid >> 4][tid & 15] = delta[(base + t0 + (tid >> 4)) * DI + d0 + (tid & 15)];
        } else {
            int jj = tid - 256;
            su[jj >> 4][jj & 15] = uact[(base + t0 + (jj >> 4)) * DI + d0 + (jj & 15)];
        }
        __syncthreads();
#pragma unroll 4
        for (int tt = 0; tt < 16; tt++) {
            float dt  = sdt[tt][w];
            float dtu = dt * su[tt][w];
            float dA0 = __expf(dt * a0);
            float dA1 = __expf(dt * a1);
            h0 = fmaf(h0, dA0, dtu * sB[tt][l]);
            h1 = fmaf(h1, dA1, dtu * sB[tt][l + 32]);
            float yv = h0 * sC[tt][l] + h1 * sC[tt][l + 32];
#pragma unroll
            for (int offx = 16; offx > 0; offx >>= 1)
                yv += __shfl_xor_sync(0xffffffffu, yv, offx);
            if (l == 0) y[(base + t0 + tt) * DI + d] = yv;
        }
    }
}

// ---------------- gate: y = (y + uact*D) * silu(z) ---------------------------
__global__ void gate_k(float* __restrict__ y, const float* __restrict__ uact,
                       const float* __restrict__ xz, const float* __restrict__ Dssm)
{
    int idx = blockIdx.x * 256 + threadIdx.x;
    int r = idx >> 10, j = idx & 1023;
    float z  = xz[(size_t)r * (2*DI) + DI + j];
    float yv = y[idx] + uact[idx] * Dssm[j];
    y[idx] = yv * (z / (1.f + expf(-z)));
}

// ---------------- fused residual-sum + LN1 + LN2 -----------------------------
__device__ __forceinline__ float blockSum128(float v, float* sm)
{
#pragma unroll
    for (int offx = 16; offx > 0; offx >>= 1)
        v += __shfl_xor_sync(0xffffffffu, v, offx);
    if ((threadIdx.x & 31) == 0) sm[threadIdx.x >> 5] = v;
    __syncthreads();
    float r = sm[0] + sm[1] + sm[2] + sm[3];
    __syncthreads();
    return r;
}

__global__ __launch_bounds__(128) void combine_ln_k(
    const float* __restrict__ xf, const float* __restrict__ attn,
    const float* __restrict__ mamba,
    const float* __restrict__ g1, const float* __restrict__ b1,
    const float* __restrict__ g2, const float* __restrict__ b2,
    float* __restrict__ h, float* __restrict__ hn)
{
    __shared__ float sm[4];
    int r = blockIdx.x, tid = threadIdx.x;
    size_t base = (size_t)r * Dd;
    float vv[4];
#pragma unroll
    for (int i = 0; i < 4; i++) {
        int c = tid + i*128;
        vv[i] = xf[base+c] + attn[base+c] + mamba[base+c];
    }
    float s = vv[0] + vv[1] + vv[2] + vv[3];
    float mean = blockSum128(s, sm) * (1.f/512.f);
    float sq = 0.f;
#pragma unroll
    for (int i = 0; i < 4; i++) { float dd = vv[i] - mean; sq = fmaf(dd, dd, sq); }
    float var = blockSum128(sq, sm) * (1.f/512.f);
    float inv = rsqrtf(var + 1e-5f);
    float hv[4];
#pragma unroll
    for (int i = 0; i < 4; i++) {
        int c = tid + i*128;
        hv[i] = (vv[i] - mean) * inv * g1[c] + b1[c];
        h[base+c] = hv[i];
    }
    float s2 = hv[0] + hv[1] + hv[2] + hv[3];
    float mean2 = blockSum128(s2, sm) * (1.f/512.f);
    float sq2 = 0.f;
#pragma unroll
    for (int i = 0; i < 4; i++) { float dd = hv[i] - mean2; sq2 = fmaf(dd, dd, sq2); }
    float var2 = blockSum128(sq2, sm) * (1.f/512.f);
    float inv2 = rsqrtf(var2 + 1e-6f);
#pragma unroll
    for (int i = 0; i < 4; i++) {
        int c = tid + i*128;
        hn[base+c] = (hv[i] - mean2) * inv2 * g2[c] + b2[c];
    }
}

// ---------------- launch -----------------------------------------------------
extern "C" void kernel_launch(void* const* d_in, const int* in_sizes, int n_in,
                              void* d_out, int out_size)
{
    const float* x            = (const float*)d_in[0];
    const unsigned char* mask = (const unsigned char*)d_in[1];
    const float* Wq = (const float*)d_in[2];   const float* bq = (const float*)d_in[3];
    const float* Wk = (const float*)d_in[4];   const float* bk = (const float*)d_in[5];
    const float* Wv = (const float*)d_in[6];   const float* bv = (const float*)d_in[7];
    const float* Wo = (const float*)d_in[8];   const float* bo = (const float*)d_in[9];
    const float* in_proj_w = (const float*)d_in[10];
    const float* conv_w    = (const float*)d_in[11];
    const float* conv_b    = (const float*)d_in[12];
    const float* x_proj_w  = (const float*)d_in[13];
    const float* dt_proj_w = (const float*)d_in[14];
    const float* dt_proj_b = (const float*)d_in[15];
    const float* A_log     = (const float*)d_in[16];
    const float* D_ssm     = (const float*)d_in[17];
    const float* out_proj_w= (const float*)d_in[18];
    const float* ln1_g = (const float*)d_in[19]; const float* ln1_b = (const float*)d_in[20];
    const float* ffn_w1= (const float*)d_in[21]; const float* ffn_b1= (const float*)d_in[22];
    const float* ffn_w2= (const float*)d_in[23]; const float* ffn_b2= (const float*)d_in[24];
    const float* ln2_g = (const float*)d_in[25]; const float* ln2_b = (const float*)d_in[26];
    float* out = (float*)d_out;

    float *q,*k,*v,*attnO,*attn_out,*xz,*uact,*xdbc,*delta,*y,*mamba,*h,*hn,*mid;
    cudaGetSymbolAddress((void**)&q,        g_q);
    cudaGetSymbolAddress((void**)&k,        g_k);
    cudaGetSymbolAddress((void**)&v,        g_v);
    cudaGetSymbolAddress((void**)&attnO,    g_attnO);
    cudaGetSymbolAddress((void**)&attn_out, g_attn_out);
    cudaGetSymbolAddress((void**)&xz,       g_xz);
    cudaGetSymbolAddress((void**)&uact,     g_uact);
    cudaGetSymbolAddress((void**)&xdbc,     g_xdbc);
    cudaGetSymbolAddress((void**)&delta,    g_delta);
    cudaGetSymbolAddress((void**)&y,        g_y);
    cudaGetSymbolAddress((void**)&mamba,    g_mamba);
    cudaGetSymbolAddress((void**)&h,        g_h);
    cudaGetSymbolAddress((void**)&hn,       g_hn);
    cudaGetSymbolAddress((void**)&mid,      g_mid);

    const int MY = Mrows / 128;   // 72
    const int attn_smem = (2*64*68 + 8*16*68) * 4;   // 69632 bytes
    cudaFuncSetAttribute(attn_tc, cudaFuncAttributeMaxDynamicSharedMemorySize, attn_smem);

    // attention branch
    gemm_tf32<EPI_NONE><<<dim3(Dd/64,   MY), 256>>>(x, Dd, Wq, bq, nullptr, q, Mrows, Dd, Dd);
    gemm_tf32<EPI_NONE><<<dim3(Dd/64,   MY), 256>>>(x, Dd, Wk, bk, nullptr, k, Mrows, Dd, Dd);
    gemm_tf32<EPI_NONE><<<dim3(Dd/64,   MY), 256>>>(x, Dd, Wv, bv, nullptr, v, Mrows, Dd, Dd);
    attn_tc<<<dim3(LL/128, Hh, Bsz), 256, attn_smem>>>(q, k, v, mask, attnO);
    gemm_tf32<EPI_NONE><<<dim3(Dd/64,   MY), 256>>>(attnO, Dd, Wo, bo, nullptr, attn_out, Mrows, Dd, Dd);

    // mamba branch
    gemm_tf32<EPI_NONE><<<dim3(2*DI/64, MY), 256>>>(x, Dd, in_proj_w, nullptr, nullptr, xz, Mrows, 2*DI, Dd);
    conv_silu_k<<<Mrows*DI/256, 256>>>(xz, conv_w, conv_b, uact);
    gemm_tf32<EPI_NONE><<<dim3(3,       MY), 256>>>(uact, DI, x_proj_w, nullptr, nullptr, xdbc, Mrows, 160, DI);
    gemm_tf32<EPI_SOFTPLUS><<<dim3(DI/64, MY), 256>>>(xdbc, 160, dt_proj_w, dt_proj_b, nullptr, delta, Mrows, DI, Rr);
    scan_k<<<dim3(DI/16, Bsz), 512>>>(delta, uact, xdbc, A_log, y);
    gate_k<<<Mrows*DI/256, 256>>>(y, uact, xz, D_ssm);
    gemm_tf32<EPI_NONE><<<dim3(Dd/64,   MY), 256>>>(y, DI, out_proj_w, nullptr, nullptr, mamba, Mrows, Dd, DI);

    // combine + double layernorm
    combine_ln_k<<<Mrows, 128>>>(x, attn_out, mamba, ln1_g, ln1_b, ln2_g, ln2_b, h, hn);

    // FFN
    gemm_tf32<EPI_GELU><<<dim3(DFF/64, MY), 256>>>(hn, Dd, ffn_w1, ffn_b1, nullptr, mid, Mrows, DFF, Dd);
    gemm_tf32<EPI_ADD><<<dim3(Dd/64,   MY), 256>>>(mid, DFF, ffn_w2, ffn_b2, h, out, Mrows, Dd, DFF);
}

// round 7
// speedup vs baseline: 3.0597x; 1.2756x over previous
#include <cuda_runtime.h>
#include <cuda_bf16.h>
#include <math.h>

#define Bsz 8
#define Dd 512
#define Hh 8
#define Ee 64
#define DI 1024
#define Ss 64
#define Rr 32
#define DFF 2048
#define LL 1152
#define Mrows (Bsz*LL)   /* 9216 */

// ---------------- scratch (static __device__, no allocation) ----------------
__device__ float g_q[Mrows*Dd];
__device__ float g_k[Mrows*Dd];
__device__ float g_v[Mrows*Dd];
__device__ float g_attnO[Mrows*Dd];
__device__ float g_attn_out[Mrows*Dd];
__device__ float g_xz[Mrows*2*DI];
__device__ float g_uact[Mrows*DI];
__device__ float g_xdbc[Mrows*160];
__device__ float g_delta[Mrows*DI];
__device__ float g_y[Mrows*DI];
__device__ float g_mamba[Mrows*Dd];
__device__ float g_h[Mrows*Dd];
__device__ float g_hn[Mrows*Dd];
__device__ float g_mid[Mrows*DFF];

enum { EPI_NONE = 0, EPI_SOFTPLUS = 1, EPI_GELU = 2, EPI_ADD = 3 };

__device__ __forceinline__ unsigned f2tf32(float f)
{
    unsigned u;
    asm("cvt.rna.tf32.f32 %0, %1;" : "=r"(u) : "f"(f));
    return u;
}

__device__ __forceinline__ void mma_tf32(float* c, const unsigned* a, const unsigned* b)
{
    asm volatile(
        "mma.sync.aligned.m16n8k8.row.col.f32.tf32.tf32.f32 "
        "{%0,%1,%2,%3},{%4,%5,%6,%7},{%8,%9},{%0,%1,%2,%3};"
        : "+f"(c[0]), "+f"(c[1]), "+f"(c[2]), "+f"(c[3])
        : "r"(a[0]), "r"(a[1]), "r"(a[2]), "r"(a[3]), "r"(b[0]), "r"(b[1]));
}

__device__ __forceinline__ void mma_bf16(float* c, const unsigned* a, const unsigned* b)
{
    asm volatile(
        "mma.sync.aligned.m16n8k16.row.col.f32.bf16.bf16.f32 "
        "{%0,%1,%2,%3},{%4,%5,%6,%7},{%8,%9},{%0,%1,%2,%3};"
        : "+f"(c[0]), "+f"(c[1]), "+f"(c[2]), "+f"(c[3])
        : "r"(a[0]), "r"(a[1]), "r"(a[2]), "r"(a[3]), "r"(b[0]), "r"(b[1]));
}

__device__ __forceinline__ void ldsm4(unsigned* r, unsigned saddr)
{
    asm volatile("ldmatrix.sync.aligned.m8n8.x4.shared.b16 {%0,%1,%2,%3}, [%4];"
        : "=r"(r[0]), "=r"(r[1]), "=r"(r[2]), "=r"(r[3]) : "r"(saddr));
}

__device__ __forceinline__ uint2 pack4(float4 f)
{
    __nv_bfloat162 p0 = __floats2bfloat162_rn(f.x, f.y);
    __nv_bfloat162 p1 = __floats2bfloat162_rn(f.z, f.w);
    uint2 u;
    u.x = *(unsigned*)&p0;
    u.y = *(unsigned*)&p1;
    return u;
}

// ============ bf16 tensor-core GEMM: C = A(MxK) @ W(NxK)^T (+bias,+epi) ======
// Block 128x64, BK=64 bf16 (128B rows, SW128 swizzle), double-buffered.
// 8 warps (4Mx2N), warp tile 32x32 via m16n8k16 + ldmatrix.x4.
template<int EPI>
__global__ __launch_bounds__(256) void gemm_bf16(
    const float* __restrict__ A, int lda,
    const float* __restrict__ W,
    const float* __restrict__ bias,
    const float* __restrict__ add,
    float* __restrict__ C, int M, int N, int K)
{
    __shared__ __align__(16) char sm[2*16384 + 2*8192];
    char* AsP = sm;                 // 2 x [128 rows x 128B]
    char* BsP = sm + 2*16384;       // 2 x [ 64 rows x 128B]
    const unsigned asU = (unsigned)__cvta_generic_to_shared(AsP);
    const unsigned bsU = (unsigned)__cvta_generic_to_shared(BsP);

    const int tid = threadIdx.x;
    const int lane = tid & 31, w = tid >> 5;
    const int warpM = w & 3, warpN = w >> 2;
    const int m0 = blockIdx.y * 128, n0 = blockIdx.x * 64;

    // -------- staging maps --------
    const int arow0 = tid >> 4;          // 0..15
    const int akq   = (tid & 15) * 4;    // 0..60
    const float* Ap = A + (size_t)(m0 + arow0) * lda + akq;
    const int aso0 = arow0*128 + (((akq >> 3) ^ (arow0 & 7)) << 4) + (akq & 7)*2;

    const float* Bp = W + (size_t)(n0 + arow0) * K + akq;
    const int bso0 = aso0;               // same formula
    bool bnv[4];
#pragma unroll
    for (int i = 0; i < 4; i++) bnv[i] = (n0 + arow0 + 16*i) < N;

    // -------- ldmatrix lane geometry --------
    const int lr = (lane & 7) + ((lane >> 3) & 1) * 8;   // 0..15
    const int ko = (lane >> 4);                           // 0/1
    int rA[2], mA[2];
#pragma unroll
    for (int mi = 0; mi < 2; mi++) {
        int r = warpM*32 + mi*16 + lr;
        rA[mi] = r * 128; mA[mi] = r & 7;
    }
    int rB[2], mB[2];
#pragma unroll
    for (int nh = 0; nh < 2; nh++) {
        int r = warpN*32 + nh*16 + lr;
        rB[nh] = r * 128; mB[nh] = r & 7;
    }

    float acc[2][4][4];
#pragma unroll
    for (int mi = 0; mi < 2; mi++)
#pragma unroll
        for (int nf = 0; nf < 4; nf++)
#pragma unroll
            for (int j = 0; j < 4; j++) acc[mi][nf][j] = 0.f;

    const int nk = (K + 63) >> 6;
    float4 ar[8], br[4];

    // prologue: tile 0
    {
        const bool av = akq < K;
#pragma unroll
        for (int i = 0; i < 8; i++)
            ar[i] = av ? *(const float4*)(Ap + (size_t)i*16*lda) : make_float4(0.f,0.f,0.f,0.f);
#pragma unroll
        for (int i = 0; i < 4; i++)
            br[i] = (bnv[i] && av) ? *(const float4*)(Bp + (size_t)i*16*K) : make_float4(0.f,0.f,0.f,0.f);
#pragma unroll
        for (int i = 0; i < 8; i++) *(uint2*)(AsP + aso0 + i*2048) = pack4(ar[i]);
#pragma unroll
        for (int i = 0; i < 4; i++) *(uint2*)(BsP + bso0 + i*2048) = pack4(br[i]);
    }
    __syncthreads();

    for (int kt = 0; kt < nk; kt++) {
        const int cur = kt & 1;
        const bool more = (kt + 1) < nk;
        if (more) {
            const int kof = (kt + 1) << 6;
            const bool av = (akq + kof) < K;
#pragma unroll
            for (int i = 0; i < 8; i++)
                ar[i] = av ? *(const float4*)(Ap + kof + (size_t)i*16*lda) : make_float4(0.f,0.f,0.f,0.f);
#pragma unroll
            for (int i = 0; i < 4; i++)
                br[i] = (bnv[i] && av) ? *(const float4*)(Bp + kof + (size_t)i*16*K) : make_float4(0.f,0.f,0.f,0.f);
        }

        const unsigned aB = asU + cur*16384;
        const unsigned bB = bsU + cur*8192;
#pragma unroll
        for (int ks = 0; ks < 4; ks++) {
            const int kx = 2*ks + ko;
            unsigned afr[2][4], bfr[2][4];
#pragma unroll
            for (int mi = 0; mi < 2; mi++)
                ldsm4(afr[mi], aB + rA[mi] + ((kx ^ mA[mi]) << 4));
#pragma unroll
            for (int nh = 0; nh < 2; nh++)
                ldsm4(bfr[nh], bB + rB[nh] + ((kx ^ mB[nh]) << 4));
#pragma unroll
            for (int mi = 0; mi < 2; mi++) {
                unsigned b0[2] = {bfr[0][0], bfr[0][2]};
                unsigned b1[2] = {bfr[0][1], bfr[0][3]};
                unsigned b2[2] = {bfr[1][0], bfr[1][2]};
                unsigned b3[2] = {bfr[1][1], bfr[1][3]};
                mma_bf16(acc[mi][0], afr[mi], b0);
                mma_bf16(acc[mi][1], afr[mi], b1);
                mma_bf16(acc[mi][2], afr[mi], b2);
                mma_bf16(acc[mi][3], afr[mi], b3);
            }
        }

        if (more) {
            const int nxt = cur ^ 1;
#pragma unroll
            for (int i = 0; i < 8; i++) *(uint2*)(AsP + nxt*16384 + aso0 + i*2048) = pack4(ar[i]);
#pragma unroll
            for (int i = 0; i < 4; i++) *(uint2*)(BsP + nxt*8192  + bso0 + i*2048) = pack4(br[i]);
            __syncthreads();
        }
    }

    // -------- epilogue --------
#pragma unroll
    for (int mi = 0; mi < 2; mi++) {
#pragma unroll
        for (int nf = 0; nf < 4; nf++) {
            int row = m0 + warpM*32 + mi*16 + (lane >> 2);
            int col = n0 + warpN*32 + nf*8 + (lane & 3)*2;
            if (col < N) {
                float v00 = acc[mi][nf][0], v01 = acc[mi][nf][1];
                float v10 = acc[mi][nf][2], v11 = acc[mi][nf][3];
                if (bias) {
                    float b0 = bias[col], b1 = bias[col+1];
                    v00 += b0; v01 += b1; v10 += b0; v11 += b1;
                }
                if (EPI == EPI_SOFTPLUS) {
                    v00 = (v00 > 20.f) ? v00 : log1pf(expf(v00));
                    v01 = (v01 > 20.f) ? v01 : log1pf(expf(v01));
                    v10 = (v10 > 20.f) ? v10 : log1pf(expf(v10));
                    v11 = (v11 > 20.f) ? v11 : log1pf(expf(v11));
                } else if (EPI == EPI_GELU) {
                    v00 = 0.5f*v00*(1.f + erff(v00*0.7071067811865475f));
                    v01 = 0.5f*v01*(1.f + erff(v01*0.7071067811865475f));
                    v10 = 0.5f*v10*(1.f + erff(v10*0.7071067811865475f));
                    v11 = 0.5f*v11*(1.f + erff(v11*0.7071067811865475f));
                } else if (EPI == EPI_ADD) {
                    const float* ap0 = add + (size_t)row * N + col;
                    const float* ap1 = add + (size_t)(row+8) * N + col;
                    v00 += ap0[0]; v01 += ap0[1]; v10 += ap1[0]; v11 += ap1[1];
                }
                *(float2*)&C[(size_t)row * N + col]     = make_float2(v00, v01);
                *(float2*)&C[(size_t)(row+8) * N + col] = make_float2(v10, v11);
            }
        }
    }
}

// ============== tf32 tensor-core flash attention =============================
__global__ __launch_bounds__(256) void attn_tc(
    const float* __restrict__ q, const float* __restrict__ k,
    const float* __restrict__ v, const unsigned char* __restrict__ mask,
    float* __restrict__ o)
{
    extern __shared__ unsigned sm_u[];
    unsigned* Ks = sm_u;                 // [64][68]
    unsigned* Vs = sm_u + 64*68;         // [64][68]
    const int tid = threadIdx.x;
    const int lane = tid & 31, w = tid >> 5;
    unsigned* Ps = sm_u + 2*64*68 + w*16*68;   // per-warp [16][68]
    const int s = lane >> 2, off = lane & 3;

    const int qt = blockIdx.x, h = blockIdx.y, b = blockIdx.z;
    const size_t bL = (size_t)b * LL;
    const int qr = qt * 128 + w * 16;

    unsigned qa[8][4];
    {
        const float* qp = q + (bL + qr) * Dd + h * Ee;
#pragma unroll
        for (int ks = 0; ks < 8; ks++) {
            qa[ks][0] = f2tf32(0.125f * qp[(size_t)(s    ) * Dd + ks*8 + off    ]);
            qa[ks][1] = f2tf32(0.125f * qp[(size_t)(s + 8) * Dd + ks*8 + off    ]);
            qa[ks][2] = f2tf32(0.125f * qp[(size_t)(s    ) * Dd + ks*8 + off + 4]);
            qa[ks][3] = f2tf32(0.125f * qp[(size_t)(s + 8) * Dd + ks*8 + off + 4]);
        }
    }

    float oa[8][4];
#pragma unroll
    for (int et = 0; et < 8; et++)
#pragma unroll
        for (int j = 0; j < 4; j++) oa[et][j] = 0.f;
    float m0v = -INFINITY, m1v = -INFINITY, l0v = 0.f, l1v = 0.f;

    for (int n0k = 0; n0k < LL; n0k += 64) {
        __syncthreads();
#pragma unroll
        for (int i = 0; i < 4; i++) {
            int u = tid + i*256;
            int row = u >> 4, qc = (u & 15) * 4;
            size_t gr = (bL + n0k + row) * Dd + h*Ee + qc;
            float4 kv = *(const float4*)&k[gr];
            *(uint4*)&Ks[row*68 + qc] = make_uint4(f2tf32(kv.x), f2tf32(kv.y), f2tf32(kv.z), f2tf32(kv.w));
            float4 vv = *(const float4*)&v[gr];
            *(uint4*)&Vs[row*68 + qc] = make_uint4(f2tf32(vv.x), f2tf32(vv.y), f2tf32(vv.z), f2tf32(vv.w));
        }
        __syncthreads();

        float sa[8][4];
#pragma unroll
        for (int nt = 0; nt < 8; nt++)
#pragma unroll
            for (int j = 0; j < 4; j++) sa[nt][j] = 0.f;
#pragma unroll
        for (int ks = 0; ks < 8; ks++) {
#pragma unroll
            for (int nt = 0; nt < 8; nt++) {
                unsigned bf[2];
                bf[0] = Ks[(nt*8 + s)*68 + ks*8 + off];
                bf[1] = Ks[(nt*8 + s)*68 + ks*8 + off + 4];
                mma_tf32(sa[nt], qa[ks], bf);
            }
        }

        float rmax0 = -INFINITY, rmax1 = -INFINITY;
#pragma unroll
        for (int nt = 0; nt < 8; nt++) {
            unsigned char mk0 = mask[bL + n0k + nt*8 + off*2];
            unsigned char mk1 = mask[bL + n0k + nt*8 + off*2 + 1];
            if (mk0) { sa[nt][0] = -INFINITY; sa[nt][2] = -INFINITY; }
            if (mk1) { sa[nt][1] = -INFINITY; sa[nt][3] = -INFINITY; }
            rmax0 = fmaxf(rmax0, fmaxf(sa[nt][0], sa[nt][1]));
            rmax1 = fmaxf(rmax1, fmaxf(sa[nt][2], sa[nt][3]));
        }
        rmax0 = fmaxf(rmax0, __shfl_xor_sync(0xffffffffu, rmax0, 1));
        rmax0 = fmaxf(rmax0, __shfl_xor_sync(0xffffffffu, rmax0, 2));
        rmax1 = fmaxf(rmax1, __shfl_xor_sync(0xffffffffu, rmax1, 1));
        rmax1 = fmaxf(rmax1, __shfl_xor_sync(0xffffffffu, rmax1, 2));
        float mn0 = fmaxf(m0v, rmax0), mn1 = fmaxf(m1v, rmax1);
        float c0 = __expf(m0v - mn0), c1 = __expf(m1v - mn1);
        float rs0 = 0.f, rs1 = 0.f;
#pragma unroll
        for (int nt = 0; nt < 8; nt++) {
            float p0 = __expf(sa[nt][0] - mn0);
            float p1 = __expf(sa[nt][1] - mn0);
            float p2 = __expf(sa[nt][2] - mn1);
            float p3 = __expf(sa[nt][3] - mn1);
            rs0 += p0 + p1; rs1 += p2 + p3;
            Ps[ s     *68 + nt*8 + off*2    ] = f2tf32(p0);
            Ps[ s     *68 + nt*8 + off*2 + 1] = f2tf32(p1);
            Ps[(s + 8)*68 + nt*8 + off*2    ] = f2tf32(p2);
            Ps[(s + 8)*68 + nt*8 + off*2 + 1] = f2tf32(p3);
        }
        rs0 += __shfl_xor_sync(0xffffffffu, rs0, 1);
        rs0 += __shfl_xor_sync(0xffffffffu, rs0, 2);
        rs1 += __shfl_xor_sync(0xffffffffu, rs1, 1);
        rs1 += __shfl_xor_sync(0xffffffffu, rs1, 2);
        l0v = l0v * c0 + rs0; l1v = l1v * c1 + rs1;
        m0v = mn0; m1v = mn1;
#pragma unroll
        for (int et = 0; et < 8; et++) {
            oa[et][0] *= c0; oa[et][1] *= c0;
            oa[et][2] *= c1; oa[et][3] *= c1;
        }
        __syncwarp();

#pragma unroll
        for (int ks = 0; ks < 8; ks++) {
            unsigned pa[4];
            pa[0] = Ps[ s     *68 + ks*8 + off    ];
            pa[1] = Ps[(s + 8)*68 + ks*8 + off    ];
            pa[2] = Ps[ s     *68 + ks*8 + off + 4];
            pa[3] = Ps[(s + 8)*68 + ks*8 + off + 4];
#pragma unroll
            for (int et = 0; et < 8; et++) {
                unsigned bf[2];
                bf[0] = Vs[(ks*8 + off    )*68 + et*8 + s];
                bf[1] = Vs[(ks*8 + off + 4)*68 + et*8 + s];
                mma_tf32(oa[et], pa, bf);
            }
        }
    }

    float inv0 = 1.f / l0v, inv1 = 1.f / l1v;
#pragma unroll
    for (int et = 0; et < 8; et++) {
        size_t r0 = (bL + qr + s    ) * Dd + h*Ee + et*8 + off*2;
        size_t r1 = (bL + qr + s + 8) * Dd + h*Ee + et*8 + off*2;
        *(float2*)&o[r0] = make_float2(oa[et][0]*inv0, oa[et][1]*inv0);
        *(float2*)&o[r1] = make_float2(oa[et][2]*inv1, oa[et][3]*inv1);
    }
}

// ---------------- causal depthwise conv (KC=4) + SiLU ------------------------
__global__ void conv_silu_k(const float* __restrict__ xz,
                            const float* __restrict__ cw,
                            const float* __restrict__ cb,
                            float* __restrict__ uact)
{
    int idx = blockIdx.x * 256 + threadIdx.x;
    int r = idx >> 10;
    int j = idx & 1023;
    int t = r % LL;
    float acc = cb[j];
#pragma unroll
    for (int kk = 0; kk < 4; kk++) {
        int tt = t + kk - 3;
        if (tt >= 0)
            acc = fmaf(xz[(size_t)(r + kk - 3) * (2*DI) + j], cw[j*4 + kk], acc);
    }
    uact[idx] = acc / (1.f + expf(-acc));
}

// ---------------- selective scan: 1 warp per (b,d), 2 states/lane ------------
__global__ __launch_bounds__(512) void scan_k(
    const float* __restrict__ delta, const float* __restrict__ uact,
    const float* __restrict__ xdbc, const float* __restrict__ A_log,
    float* __restrict__ y)
{
    __shared__ float sB[16][64];
    __shared__ float sC[16][64];
    __shared__ float sdt[16][16];
    __shared__ float su[16][16];

    int b = blockIdx.y;
    int d0 = blockIdx.x * 16;
    int tid = threadIdx.x;
    int w = tid >> 5, l = tid & 31;
    int d = d0 + w;
    float a0 = -expf(A_log[d*Ss + l]);
    float a1 = -expf(A_log[d*Ss + l + 32]);
    float h0 = 0.f, h1 = 0.f;
    size_t base = (size_t)b * LL;

    for (int t0 = 0; t0 < LL; t0 += 16) {
        __syncthreads();
        for (int i = tid; i < 2048; i += 512) {
            int tt = i >> 7, c = i & 127;
            float val = xdbc[(base + t0 + tt) * 160 + 32 + c];
            if (c < 64) sB[tt][c] = val; else sC[tt][c - 64] = val;
        }
        if (tid < 256) {
            sdt[tid >> 4][tid & 15] = delta[(base + t0 + (tid >> 4)) * DI + d0 + (tid & 15)];
        } else {
            int jj = tid - 256;
            su[jj >> 4][jj & 15] = uact[(base + t0 + (jj >> 4)) * DI + d0 + (jj & 15)];
        }
        __syncthreads();
#pragma unroll 4
        for (int tt = 0; tt < 16; tt++) {
            float dt  = sdt[tt][w];
            float dtu = dt * su[tt][w];
            float dA0 = __expf(dt * a0);
            float dA1 = __expf(dt * a1);
            h0 = fmaf(h0, dA0, dtu * sB[tt][l]);
            h1 = fmaf(h1, dA1, dtu * sB[tt][l + 32]);
            float yv = h0 * sC[tt][l] + h1 * sC[tt][l + 32];
#pragma unroll
            for (int offx = 16; offx > 0; offx >>= 1)
                yv += __shfl_xor_sync(0xffffffffu, yv, offx);
            if (l == 0) y[(base + t0 + tt) * DI + d] = yv;
        }
    }
}

// ---------------- gate: y = (y + uact*D) * silu(z) ---------------------------
__global__ void gate_k(float* __restrict__ y, const float* __restrict__ uact,
                       const float* __restrict__ xz, const float* __restrict__ Dssm)
{
    int idx = blockIdx.x * 256 + threadIdx.x;
    int r = idx >> 10, j = idx & 1023;
    float z  = xz[(size_t)r * (2*DI) + DI + j];
    float yv = y[idx] + uact[idx] * Dssm[j];
    y[idx] = yv * (z / (1.f + expf(-z)));
}

// ---------------- fused residual-sum + LN1 + LN2 -----------------------------
__device__ __forceinline__ float blockSum128(float v, float* sm)
{
#pragma unroll
    for (int offx = 16; offx > 0; offx >>= 1)
        v += __shfl_xor_sync(0xffffffffu, v, offx);
    if ((threadIdx.x & 31) == 0) sm[threadIdx.x >> 5] = v;
    __syncthreads();
    float r = sm[0] + sm[1] + sm[2] + sm[3];
    __syncthreads();
    return r;
}

__global__ __launch_bounds__(128) void combine_ln_k(
    const float* __restrict__ xf, const float* __restrict__ attn,
    const float* __restrict__ mamba,
    const float* __restrict__ g1, const float* __restrict__ b1,
    const float* __restrict__ g2, const float* __restrict__ b2,
    float* __restrict__ h, float* __restrict__ hn)
{
    __shared__ float sm[4];
    int r = blockIdx.x, tid = threadIdx.x;
    size_t base = (size_t)r * Dd;
    float vv[4];
#pragma unroll
    for (int i = 0; i < 4; i++) {
        int c = tid + i*128;
        vv[i] = xf[base+c] + attn[base+c] + mamba[base+c];
    }
    float s = vv[0] + vv[1] + vv[2] + vv[3];
    float mean = blockSum128(s, sm) * (1.f/512.f);
    float sq = 0.f;
#pragma unroll
    for (int i = 0; i < 4; i++) { float dd = vv[i] - mean; sq = fmaf(dd, dd, sq); }
    float var = blockSum128(sq, sm) * (1.f/512.f);
    float inv = rsqrtf(var + 1e-5f);
    float hv[4];
#pragma unroll
    for (int i = 0; i < 4; i++) {
        int c = tid + i*128;
        hv[i] = (vv[i] - mean) * inv * g1[c] + b1[c];
        h[base+c] = hv[i];
    }
    float s2 = hv[0] + hv[1] + hv[2] + hv[3];
    float mean2 = blockSum128(s2, sm) * (1.f/512.f);
    float sq2 = 0.f;
#pragma unroll
    for (int i = 0; i < 4; i++) { float dd = hv[i] - mean2; sq2 = fmaf(dd, dd, sq2); }
    float var2 = blockSum128(sq2, sm) * (1.f/512.f);
    float inv2 = rsqrtf(var2 + 1e-6f);
#pragma unroll
    for (int i = 0; i < 4; i++) {
        int c = tid + i*128;
        hn[base+c] = (hv[i] - mean2) * inv2 * g2[c] + b2[c];
    }
}

// ---------------- launch -----------------------------------------------------
extern "C" void kernel_launch(void* const* d_in, const int* in_sizes, int n_in,
                              void* d_out, int out_size)
{
    const float* x            = (const float*)d_in[0];
    const unsigned char* mask = (const unsigned char*)d_in[1];
    const float* Wq = (const float*)d_in[2];   const float* bq = (const float*)d_in[3];
    const float* Wk = (const float*)d_in[4];   const float* bk = (const float*)d_in[5];
    const float* Wv = (const float*)d_in[6];   const float* bv = (const float*)d_in[7];
    const float* Wo = (const float*)d_in[8];   const float* bo = (const float*)d_in[9];
    const float* in_proj_w = (const float*)d_in[10];
    const float* conv_w    = (const float*)d_in[11];
    const float* conv_b    = (const float*)d_in[12];
    const float* x_proj_w  = (const float*)d_in[13];
    const float* dt_proj_w = (const float*)d_in[14];
    const float* dt_proj_b = (const float*)d_in[15];
    const float* A_log     = (const float*)d_in[16];
    const float* D_ssm     = (const float*)d_in[17];
    const float* out_proj_w= (const float*)d_in[18];
    const float* ln1_g = (const float*)d_in[19]; const float* ln1_b = (const float*)d_in[20];
    const float* ffn_w1= (const float*)d_in[21]; const float* ffn_b1= (const float*)d_in[22];
    const float* ffn_w2= (const float*)d_in[23]; const float* ffn_b2= (const float*)d_in[24];
    const float* ln2_g = (const float*)d_in[25]; const float* ln2_b = (const float*)d_in[26];
    float* out = (float*)d_out;

    float *q,*k,*v,*attnO,*attn_out,*xz,*uact,*xdbc,*delta,*y,*mamba,*h,*hn,*mid;
    cudaGetSymbolAddress((void**)&q,        g_q);
    cudaGetSymbolAddress((void**)&k,        g_k);
    cudaGetSymbolAddress((void**)&v,        g_v);
    cudaGetSymbolAddress((void**)&attnO,    g_attnO);
    cudaGetSymbolAddress((void**)&attn_out, g_attn_out);
    cudaGetSymbolAddress((void**)&xz,       g_xz);
    cudaGetSymbolAddress((void**)&uact,     g_uact);
    cudaGetSymbolAddress((void**)&xdbc,     g_xdbc);
    cudaGetSymbolAddress((void**)&delta,    g_delta);
    cudaGetSymbolAddress((void**)&y,        g_y);
    cudaGetSymbolAddress((void**)&mamba,    g_mamba);
    cudaGetSymbolAddress((void**)&h,        g_h);
    cudaGetSymbolAddress((void**)&hn,       g_hn);
    cudaGetSymbolAddress((void**)&mid,      g_mid);

    const int MY = Mrows / 128;   // 72
    const int attn_smem = (2*64*68 + 8*16*68) * 4;   // 69632 bytes
    cudaFuncSetAttribute(attn_tc, cudaFuncAttributeMaxDynamicSharedMemorySize, attn_smem);

    // attention branch
    gemm_bf16<EPI_NONE><<<dim3(Dd/64,   MY), 256>>>(x, Dd, Wq, bq, nullptr, q, Mrows, Dd, Dd);
    gemm_bf16<EPI_NONE><<<dim3(Dd/64,   MY), 256>>>(x, Dd, Wk, bk, nullptr, k, Mrows, Dd, Dd);
    gemm_bf16<EPI_NONE><<<dim3(Dd/64,   MY), 256>>>(x, Dd, Wv, bv, nullptr, v, Mrows, Dd, Dd);
    attn_tc<<<dim3(LL/128, Hh, Bsz), 256, attn_smem>>>(q, k, v, mask, attnO);
    gemm_bf16<EPI_NONE><<<dim3(Dd/64,   MY), 256>>>(attnO, Dd, Wo, bo, nullptr, attn_out, Mrows, Dd, Dd);

    // mamba branch
    gemm_bf16<EPI_NONE><<<dim3(2*DI/64, MY), 256>>>(x, Dd, in_proj_w, nullptr, nullptr, xz, Mrows, 2*DI, Dd);
    conv_silu_k<<<Mrows*DI/256, 256>>>(xz, conv_w, conv_b, uact);
    gemm_bf16<EPI_NONE><<<dim3(3,       MY), 256>>>(uact, DI, x_proj_w, nullptr, nullptr, xdbc, Mrows, 160, DI);
    gemm_bf16<EPI_SOFTPLUS><<<dim3(DI/64, MY), 256>>>(xdbc, 160, dt_proj_w, dt_proj_b, nullptr, delta, Mrows, DI, Rr);
    scan_k<<<dim3(DI/16, Bsz), 512>>>(delta, uact, xdbc, A_log, y);
    gate_k<<<Mrows*DI/256, 256>>>(y, uact, xz, D_ssm);
    gemm_bf16<EPI_NONE><<<dim3(Dd/64,   MY), 256>>>(y, DI, out_proj_w, nullptr, nullptr, mamba, Mrows, Dd, DI);

    // combine + double layernorm
    combine_ln_k<<<Mrows, 128>>>(x, attn_out, mamba, ln1_g, ln1_b, ln2_g, ln2_b, h, hn);

    // FFN
    gemm_bf16<EPI_GELU><<<dim3(DFF/64, MY), 256>>>(hn, Dd, ffn_w1, ffn_b1, nullptr, mid, Mrows, DFF, Dd);
    gemm_bf16<EPI_ADD><<<dim3(Dd/64,   MY), 256>>>(mid, DFF, ffn_w2, ffn_b2, h, out, Mrows, Dd, DFF);
}

// round 9
// speedup vs baseline: 3.1283x; 1.0224x over previous
#include <cuda_runtime.h>
#include <cuda_bf16.h>
#include <math.h>

#define Bsz 8
#define Dd 512
#define Hh 8
#define Ee 64
#define DI 1024
#define Ss 64
#define Rr 32
#define DFF 2048
#define LL 1152
#define Mrows (Bsz*LL)   /* 9216 */

// ---------------- scratch (static __device__, no allocation) ----------------
__device__ float g_q[Mrows*Dd];
__device__ float g_k[Mrows*Dd];
__device__ float g_v[Mrows*Dd];
__device__ float g_attnO[Mrows*Dd];
__device__ float g_attn_out[Mrows*Dd];
__device__ float g_xz[Mrows*2*DI];
__device__ float g_uact[Mrows*DI];
__device__ float g_xdbc[Mrows*160];
__device__ float g_delta[Mrows*DI];
__device__ float g_y[Mrows*DI];
__device__ float g_mamba[Mrows*Dd];
__device__ float g_h[Mrows*Dd];
__device__ float g_hn[Mrows*Dd];
__device__ float g_mid[Mrows*DFF];

enum { EPI_NONE = 0, EPI_SOFTPLUS = 1, EPI_GELU = 2, EPI_ADD = 3 };

__device__ __forceinline__ unsigned f2tf32(float f)
{
    unsigned u;
    asm("cvt.rna.tf32.f32 %0, %1;" : "=r"(u) : "f"(f));
    return u;
}

__device__ __forceinline__ void mma_tf32(float* c, const unsigned* a, const unsigned* b)
{
    asm volatile(
        "mma.sync.aligned.m16n8k8.row.col.f32.tf32.tf32.f32 "
        "{%0,%1,%2,%3},{%4,%5,%6,%7},{%8,%9},{%0,%1,%2,%3};"
        : "+f"(c[0]), "+f"(c[1]), "+f"(c[2]), "+f"(c[3])
        : "r"(a[0]), "r"(a[1]), "r"(a[2]), "r"(a[3]), "r"(b[0]), "r"(b[1]));
}

__device__ __forceinline__ void mma_bf16(float* c, const unsigned* a, const unsigned* b)
{
    asm volatile(
        "mma.sync.aligned.m16n8k16.row.col.f32.bf16.bf16.f32 "
        "{%0,%1,%2,%3},{%4,%5,%6,%7},{%8,%9},{%0,%1,%2,%3};"
        : "+f"(c[0]), "+f"(c[1]), "+f"(c[2]), "+f"(c[3])
        : "r"(a[0]), "r"(a[1]), "r"(a[2]), "r"(a[3]), "r"(b[0]), "r"(b[1]));
}

__device__ __forceinline__ void ldsm4(unsigned* r, unsigned saddr)
{
    asm volatile("ldmatrix.sync.aligned.m8n8.x4.shared.b16 {%0,%1,%2,%3}, [%4];"
        : "=r"(r[0]), "=r"(r[1]), "=r"(r[2]), "=r"(r[3]) : "r"(saddr));
}

__device__ __forceinline__ uint2 pack4(float4 f)
{
    __nv_bfloat162 p0 = __floats2bfloat162_rn(f.x, f.y);
    __nv_bfloat162 p1 = __floats2bfloat162_rn(f.z, f.w);
    uint2 u;
    u.x = *(unsigned*)&p0;
    u.y = *(unsigned*)&p1;
    return u;
}

__device__ __forceinline__ float epi_apply_scalar(int EPI, float v)
{
    if (EPI == EPI_SOFTPLUS) return (v > 20.f) ? v : log1pf(expf(v));
    if (EPI == EPI_GELU)     return 0.5f*v*(1.f + erff(v*0.7071067811865475f));
    return v;
}

// ============ bf16 tensor-core GEMM: C = A(MxK) @ W(NxK)^T (+bias,+epi) ======
template<int EPI>
__global__ __launch_bounds__(256) void gemm_bf16(
    const float* __restrict__ A, int lda,
    const float* __restrict__ W,
    const float* __restrict__ bias,
    const float* __restrict__ add,
    float* __restrict__ C, int M, int N, int K)
{
    __shared__ __align__(16) char sm[2*16384 + 2*8192];
    char* AsP = sm;
    char* BsP = sm + 2*16384;
    const unsigned asU = (unsigned)__cvta_generic_to_shared(AsP);
    const unsigned bsU = (unsigned)__cvta_generic_to_shared(BsP);

    const int tid = threadIdx.x;
    const int lane = tid & 31, w = tid >> 5;
    const int warpM = w & 3, warpN = w >> 2;
    const int m0 = blockIdx.y * 128, n0 = blockIdx.x * 64;

    const int arow0 = tid >> 4;
    const int akq   = (tid & 15) * 4;
    const float* Ap = A + (size_t)(m0 + arow0) * lda + akq;
    const int aso0 = arow0*128 + (((akq >> 3) ^ (arow0 & 7)) << 4) + (akq & 7)*2;

    const float* Bp = W + (size_t)(n0 + arow0) * K + akq;
    const int bso0 = aso0;
    bool bnv[4];
#pragma unroll
    for (int i = 0; i < 4; i++) bnv[i] = (n0 + arow0 + 16*i) < N;

    const int lr = (lane & 7) + ((lane >> 3) & 1) * 8;
    const int ko = (lane >> 4);
    int rA[2], mA[2];
#pragma unroll
    for (int mi = 0; mi < 2; mi++) {
        int r = warpM*32 + mi*16 + lr;
        rA[mi] = r * 128; mA[mi] = r & 7;
    }
    int rB[2], mB[2];
#pragma unroll
    for (int nh = 0; nh < 2; nh++) {
        int r = warpN*32 + nh*16 + lr;
        rB[nh] = r * 128; mB[nh] = r & 7;
    }

    float acc[2][4][4];
#pragma unroll
    for (int mi = 0; mi < 2; mi++)
#pragma unroll
        for (int nf = 0; nf < 4; nf++)
#pragma unroll
            for (int j = 0; j < 4; j++) acc[mi][nf][j] = 0.f;

    const int nk = (K + 63) >> 6;
    float4 ar[8], br[4];

    {
        const bool av = akq < K;
#pragma unroll
        for (int i = 0; i < 8; i++)
            ar[i] = av ? *(const float4*)(Ap + (size_t)i*16*lda) : make_float4(0.f,0.f,0.f,0.f);
#pragma unroll
        for (int i = 0; i < 4; i++)
            br[i] = (bnv[i] && av) ? *(const float4*)(Bp + (size_t)i*16*K) : make_float4(0.f,0.f,0.f,0.f);
#pragma unroll
        for (int i = 0; i < 8; i++) *(uint2*)(AsP + aso0 + i*2048) = pack4(ar[i]);
#pragma unroll
        for (int i = 0; i < 4; i++) *(uint2*)(BsP + bso0 + i*2048) = pack4(br[i]);
    }
    __syncthreads();

    for (int kt = 0; kt < nk; kt++) {
        const int cur = kt & 1;
        const bool more = (kt + 1) < nk;
        if (more) {
            const int kof = (kt + 1) << 6;
            const bool av = (akq + kof) < K;
#pragma unroll
            for (int i = 0; i < 8; i++)
                ar[i] = av ? *(const float4*)(Ap + kof + (size_t)i*16*lda) : make_float4(0.f,0.f,0.f,0.f);
#pragma unroll
            for (int i = 0; i < 4; i++)
                br[i] = (bnv[i] && av) ? *(const float4*)(Bp + kof + (size_t)i*16*K) : make_float4(0.f,0.f,0.f,0.f);
        }

        const unsigned aB = asU + cur*16384;
        const unsigned bB = bsU + cur*8192;
#pragma unroll
        for (int ks = 0; ks < 4; ks++) {
            const int kx = 2*ks + ko;
            unsigned afr[2][4], bfr[2][4];
#pragma unroll
            for (int mi = 0; mi < 2; mi++)
                ldsm4(afr[mi], aB + rA[mi] + ((kx ^ mA[mi]) << 4));
#pragma unroll
            for (int nh = 0; nh < 2; nh++)
                ldsm4(bfr[nh], bB + rB[nh] + ((kx ^ mB[nh]) << 4));
#pragma unroll
            for (int mi = 0; mi < 2; mi++) {
                unsigned b0[2] = {bfr[0][0], bfr[0][2]};
                unsigned b1[2] = {bfr[0][1], bfr[0][3]};
                unsigned b2[2] = {bfr[1][0], bfr[1][2]};
                unsigned b3[2] = {bfr[1][1], bfr[1][3]};
                mma_bf16(acc[mi][0], afr[mi], b0);
                mma_bf16(acc[mi][1], afr[mi], b1);
                mma_bf16(acc[mi][2], afr[mi], b2);
                mma_bf16(acc[mi][3], afr[mi], b3);
            }
        }

        if (more) {
            const int nxt = cur ^ 1;
#pragma unroll
            for (int i = 0; i < 8; i++) *(uint2*)(AsP + nxt*16384 + aso0 + i*2048) = pack4(ar[i]);
#pragma unroll
            for (int i = 0; i < 4; i++) *(uint2*)(BsP + nxt*8192  + bso0 + i*2048) = pack4(br[i]);
            __syncthreads();
        }
    }

#pragma unroll
    for (int mi = 0; mi < 2; mi++) {
#pragma unroll
        for (int nf = 0; nf < 4; nf++) {
            int row = m0 + warpM*32 + mi*16 + (lane >> 2);
            int col = n0 + warpN*32 + nf*8 + (lane & 3)*2;
            if (col < N) {
                float v00 = acc[mi][nf][0], v01 = acc[mi][nf][1];
                float v10 = acc[mi][nf][2], v11 = acc[mi][nf][3];
                if (bias) {
                    float b0 = bias[col], b1 = bias[col+1];
                    v00 += b0; v01 += b1; v10 += b0; v11 += b1;
                }
                if (EPI == EPI_ADD) {
                    const float* ap0 = add + (size_t)row * N + col;
                    const float* ap1 = add + (size_t)(row+8) * N + col;
                    v00 += ap0[0]; v01 += ap0[1]; v10 += ap1[0]; v11 += ap1[1];
                } else {
                    v00 = epi_apply_scalar(EPI, v00); v01 = epi_apply_scalar(EPI, v01);
                    v10 = epi_apply_scalar(EPI, v10); v11 = epi_apply_scalar(EPI, v11);
                }
                *(float2*)&C[(size_t)row * N + col]     = make_float2(v00, v01);
                *(float2*)&C[(size_t)(row+8) * N + col] = make_float2(v10, v11);
            }
        }
    }
}

// ================= tf32 tensor-core GEMM (for scan-sensitive projections) ====
template<int EPI>
__global__ __launch_bounds__(256) void gemm_tf32(
    const float* __restrict__ A, int lda,
    const float* __restrict__ W,
    const float* __restrict__ bias,
    const float* __restrict__ add,
    float* __restrict__ C, int M, int N, int K)
{
    __shared__ __align__(16) unsigned As[2][128*32];
    __shared__ __align__(16) unsigned Bs[2][64*32];

    const int t = threadIdx.x;
    const int m0 = blockIdx.y * 128, n0 = blockIdx.x * 64;
    const int lane = t & 31, w = t >> 5;
    const int warpM = w & 3, warpN = w >> 2;
    const int s = lane >> 2, off = lane & 3;

    const float* aptr[4]; int aso[4];
#pragma unroll
    for (int i = 0; i < 4; i++) {
        int e = t + i*256;
        int m = e >> 3, g = e & 7;
        aptr[i] = A + (size_t)(m0 + m) * lda + g*4;
        aso[i]  = m*32 + ((g ^ (m & 7)) << 2);
    }
    const float* bptr[2]; int bso[2]; bool bval[2];
#pragma unroll
    for (int i = 0; i < 2; i++) {
        int e = t + i*256;
        int n = e >> 3, g = e & 7;
        bval[i] = (n0 + n) < N;
        bptr[i] = W + (size_t)(n0 + n) * K + g*4;
        bso[i]  = n*32 + ((g ^ (n & 7)) << 2);
    }

    float acc[2][4][4];
#pragma unroll
    for (int mi = 0; mi < 2; mi++)
#pragma unroll
        for (int ni = 0; ni < 4; ni++)
#pragma unroll
            for (int j = 0; j < 4; j++) acc[mi][ni][j] = 0.f;

    const int nk = K >> 5;
    float4 ar[4], br[2];

#pragma unroll
    for (int i = 0; i < 4; i++) ar[i] = *(const float4*)(aptr[i]);
#pragma unroll
    for (int i = 0; i < 2; i++)
        br[i] = bval[i] ? *(const float4*)(bptr[i]) : make_float4(0.f,0.f,0.f,0.f);
#pragma unroll
    for (int i = 0; i < 4; i++)
        *(uint4*)&As[0][aso[i]] = make_uint4(f2tf32(ar[i].x), f2tf32(ar[i].y), f2tf32(ar[i].z), f2tf32(ar[i].w));
#pragma unroll
    for (int i = 0; i < 2; i++)
        *(uint4*)&Bs[0][bso[i]] = make_uint4(f2tf32(br[i].x), f2tf32(br[i].y), f2tf32(br[i].z), f2tf32(br[i].w));
    __syncthreads();

    for (int kt = 0; kt < nk; kt++) {
        const int cur = kt & 1, nxt = cur ^ 1;
        const bool more = (kt + 1) < nk;
        if (more) {
            const int ko = (kt + 1) * 32;
#pragma unroll
            for (int i = 0; i < 4; i++) ar[i] = *(const float4*)(aptr[i] + ko);
#pragma unroll
            for (int i = 0; i < 2; i++)
                br[i] = bval[i] ? *(const float4*)(bptr[i] + ko) : make_float4(0.f,0.f,0.f,0.f);
        }

#pragma unroll
        for (int ks = 0; ks < 4; ks++) {
            const int x0 = (((ks*2)     ^ s) << 2) + off;
            const int x1 = (((ks*2 + 1) ^ s) << 2) + off;
            unsigned a[2][4];
#pragma unroll
            for (int mi = 0; mi < 2; mi++) {
                int r = (warpM*32 + mi*16 + s) * 32;
                a[mi][0] = As[cur][r + x0];
                a[mi][1] = As[cur][r + 256 + x0];
                a[mi][2] = As[cur][r + x1];
                a[mi][3] = As[cur][r + 256 + x1];
            }
            unsigned b[4][2];
#pragma unroll
            for (int ni = 0; ni < 4; ni++) {
                int rb = (warpN*32 + ni*8 + s) * 32;
                b[ni][0] = Bs[cur][rb + x0];
                b[ni][1] = Bs[cur][rb + x1];
            }
#pragma unroll
            for (int mi = 0; mi < 2; mi++)
#pragma unroll
                for (int ni = 0; ni < 4; ni++)
                    mma_tf32(acc[mi][ni], a[mi], b[ni]);
        }

        if (more) {
#pragma unroll
            for (int i = 0; i < 4; i++)
                *(uint4*)&As[nxt][aso[i]] = make_uint4(f2tf32(ar[i].x), f2tf32(ar[i].y), f2tf32(ar[i].z), f2tf32(ar[i].w));
#pragma unroll
            for (int i = 0; i < 2; i++)
                *(uint4*)&Bs[nxt][bso[i]] = make_uint4(f2tf32(br[i].x), f2tf32(br[i].y), f2tf32(br[i].z), f2tf32(br[i].w));
            __syncthreads();
        }
    }

#pragma unroll
    for (int mi = 0; mi < 2; mi++) {
#pragma unroll
        for (int ni = 0; ni < 4; ni++) {
            int row = m0 + warpM*32 + mi*16 + s;
            int col = n0 + warpN*32 + ni*8 + off*2;
            if (col < N) {
                float v00 = acc[mi][ni][0], v01 = acc[mi][ni][1];
                float v10 = acc[mi][ni][2], v11 = acc[mi][ni][3];
                if (bias) {
                    float b0 = bias[col], b1 = bias[col+1];
                    v00 += b0; v01 += b1; v10 += b0; v11 += b1;
                }
                if (EPI == EPI_ADD) {
                    const float* ap0 = add + (size_t)row * N + col;
                    const float* ap1 = add + (size_t)(row+8) * N + col;
                    v00 += ap0[0]; v01 += ap0[1]; v10 += ap1[0]; v11 += ap1[1];
                } else {
                    v00 = epi_apply_scalar(EPI, v00); v01 = epi_apply_scalar(EPI, v01);
                    v10 = epi_apply_scalar(EPI, v10); v11 = epi_apply_scalar(EPI, v11);
                }
                *(float2*)&C[(size_t)row * N + col]     = make_float2(v00, v01);
                *(float2*)&C[(size_t)(row+8) * N + col] = make_float2(v10, v11);
            }
        }
    }
}

// ============== tf32 tensor-core flash attention =============================
__global__ __launch_bounds__(256) void attn_tc(
    const float* __restrict__ q, const float* __restrict__ k,
    const float* __restrict__ v, const unsigned char* __restrict__ mask,
    float* __restrict__ o)
{
    extern __shared__ unsigned sm_u[];
    unsigned* Ks = sm_u;
    unsigned* Vs = sm_u + 64*68;
    const int tid = threadIdx.x;
    const int lane = tid & 31, w = tid >> 5;
    unsigned* Ps = sm_u + 2*64*68 + w*16*68;
    const int s = lane >> 2, off = lane & 3;

    const int qt = blockIdx.x, h = blockIdx.y, b = blockIdx.z;
    const size_t bL = (size_t)b * LL;
    const int qr = qt * 128 + w * 16;

    unsigned qa[8][4];
    {
        const float* qp = q + (bL + qr) * Dd + h * Ee;
#pragma unroll
        for (int ks = 0; ks < 8; ks++) {
            qa[ks][0] = f2tf32(0.125f * qp[(size_t)(s    ) * Dd + ks*8 + off    ]);
            qa[ks][1] = f2tf32(0.125f * qp[(size_t)(s + 8) * Dd + ks*8 + off    ]);
            qa[ks][2] = f2tf32(0.125f * qp[(size_t)(s    ) * Dd + ks*8 + off + 4]);
            qa[ks][3] = f2tf32(0.125f * qp[(size_t)(s + 8) * Dd + ks*8 + off + 4]);
        }
    }

    float oa[8][4];
#pragma unroll
    for (int et = 0; et < 8; et++)
#pragma unroll
        for (int j = 0; j < 4; j++) oa[et][j] = 0.f;
    float m0v = -INFINITY, m1v = -INFINITY, l0v = 0.f, l1v = 0.f;

    for (int n0k = 0; n0k < LL; n0k += 64) {
        __syncthreads();
#pragma unroll
        for (int i = 0; i < 4; i++) {
            int u = tid + i*256;
            int row = u >> 4, qc = (u & 15) * 4;
            size_t gr = (bL + n0k + row) * Dd + h*Ee + qc;
            float4 kv = *(const float4*)&k[gr];
            *(uint4*)&Ks[row*68 + qc] = make_uint4(f2tf32(kv.x), f2tf32(kv.y), f2tf32(kv.z), f2tf32(kv.w));
            float4 vv = *(const float4*)&v[gr];
            *(uint4*)&Vs[row*68 + qc] = make_uint4(f2tf32(vv.x), f2tf32(vv.y), f2tf32(vv.z), f2tf32(vv.w));
        }
        __syncthreads();

        float sa[8][4];
#pragma unroll
        for (int nt = 0; nt < 8; nt++)
#pragma unroll
            for (int j = 0; j < 4; j++) sa[nt][j] = 0.f;
#pragma unroll
        for (int ks = 0; ks < 8; ks++) {
#pragma unroll
            for (int nt = 0; nt < 8; nt++) {
                unsigned bf[2];
                bf[0] = Ks[(nt*8 + s)*68 + ks*8 + off];
                bf[1] = Ks[(nt*8 + s)*68 + ks*8 + off + 4];
                mma_tf32(sa[nt], qa[ks], bf);
            }
        }

        float rmax0 = -INFINITY, rmax1 = -INFINITY;
#pragma unroll
        for (int nt = 0; nt < 8; nt++) {
            unsigned char mk0 = mask[bL + n0k + nt*8 + off*2];
            unsigned char mk1 = mask[bL + n0k + nt*8 + off*2 + 1];
            if (mk0) { sa[nt][0] = -INFINITY; sa[nt][2] = -INFINITY; }
            if (mk1) { sa[nt][1] = -INFINITY; sa[nt][3] = -INFINITY; }
            rmax0 = fmaxf(rmax0, fmaxf(sa[nt][0], sa[nt][1]));
            rmax1 = fmaxf(rmax1, fmaxf(sa[nt][2], sa[nt][3]));
        }
        rmax0 = fmaxf(rmax0, __shfl_xor_sync(0xffffffffu, rmax0, 1));
        rmax0 = fmaxf(rmax0, __shfl_xor_sync(0xffffffffu, rmax0, 2));
        rmax1 = fmaxf(rmax1, __shfl_xor_sync(0xffffffffu, rmax1, 1));
        rmax1 = fmaxf(rmax1, __shfl_xor_sync(0xffffffffu, rmax1, 2));
        float mn0 = fmaxf(m0v, rmax0), mn1 = fmaxf(m1v, rmax1);
        float c0 = __expf(m0v - mn0), c1 = __expf(m1v - mn1);
        float rs0 = 0.f, rs1 = 0.f;
#pragma unroll
        for (int nt = 0; nt < 8; nt++) {
            float p0 = __expf(sa[nt][0] - mn0);
            float p1 = __expf(sa[nt][1] - mn0);
            float p2 = __expf(sa[nt][2] - mn1);
            float p3 = __expf(sa[nt][3] - mn1);
            rs0 += p0 + p1; rs1 += p2 + p3;
            Ps[ s     *68 + nt*8 + off*2    ] = f2tf32(p0);
            Ps[ s     *68 + nt*8 + off*2 + 1] = f2tf32(p1);
            Ps[(s + 8)*68 + nt*8 + off*2    ] = f2tf32(p2);
            Ps[(s + 8)*68 + nt*8 + off*2 + 1] = f2tf32(p3);
        }
        rs0 += __shfl_xor_sync(0xffffffffu, rs0, 1);
        rs0 += __shfl_xor_sync(0xffffffffu, rs0, 2);
        rs1 += __shfl_xor_sync(0xffffffffu, rs1, 1);
        rs1 += __shfl_xor_sync(0xffffffffu, rs1, 2);
        l0v = l0v * c0 + rs0; l1v = l1v * c1 + rs1;
        m0v = mn0; m1v = mn1;
#pragma unroll
        for (int et = 0; et < 8; et++) {
            oa[et][0] *= c0; oa[et][1] *= c0;
            oa[et][2] *= c1; oa[et][3] *= c1;
        }
        __syncwarp();

#pragma unroll
        for (int ks = 0; ks < 8; ks++) {
            unsigned pa[4];
            pa[0] = Ps[ s     *68 + ks*8 + off    ];
            pa[1] = Ps[(s + 8)*68 + ks*8 + off    ];
            pa[2] = Ps[ s     *68 + ks*8 + off + 4];
            pa[3] = Ps[(s + 8)*68 + ks*8 + off + 4];
#pragma unroll
            for (int et = 0; et < 8; et++) {
                unsigned bf[2];
                bf[0] = Vs[(ks*8 + off    )*68 + et*8 + s];
                bf[1] = Vs[(ks*8 + off + 4)*68 + et*8 + s];
                mma_tf32(oa[et], pa, bf);
            }
        }
    }

    float inv0 = 1.f / l0v, inv1 = 1.f / l1v;
#pragma unroll
    for (int et = 0; et < 8; et++) {
        size_t r0 = (bL + qr + s    ) * Dd + h*Ee + et*8 + off*2;
        size_t r1 = (bL + qr + s + 8) * Dd + h*Ee + et*8 + off*2;
        *(float2*)&o[r0] = make_float2(oa[et][0]*inv0, oa[et][1]*inv0);
        *(float2*)&o[r1] = make_float2(oa[et][2]*inv1, oa[et][3]*inv1);
    }
}

// ---------------- causal depthwise conv (KC=4) + SiLU ------------------------
__global__ void conv_silu_k(const float* __restrict__ xz,
                            const float* __restrict__ cw,
                            const float* __restrict__ cb,
                            float* __restrict__ uact)
{
    int idx = blockIdx.x * 256 + threadIdx.x;
    int r = idx >> 10;
    int j = idx & 1023;
    int t = r % LL;
    float acc = cb[j];
#pragma unroll
    for (int kk = 0; kk < 4; kk++) {
        int tt = t + kk - 3;
        if (tt >= 0)
            acc = fmaf(xz[(size_t)(r + kk - 3) * (2*DI) + j], cw[j*4 + kk], acc);
    }
    uact[idx] = acc / (1.f + expf(-acc));
}

// ---------------- selective scan: 1 warp per (b,d), 2 states/lane ------------
__global__ __launch_bounds__(512) void scan_k(
    const float* __restrict__ delta, const float* __restrict__ uact,
    const float* __restrict__ xdbc, const float* __restrict__ A_log,
    float* __restrict__ y)
{
    __shared__ float sB[16][64];
    __shared__ float sC[16][64];
    __shared__ float sdt[16][16];
    __shared__ float su[16][16];

    int b = blockIdx.y;
    int d0 = blockIdx.x * 16;
    int tid = threadIdx.x;
    int w = tid >> 5, l = tid & 31;
    int d = d0 + w;
    float a0 = -expf(A_log[d*Ss + l]);
    float a1 = -expf(A_log[d*Ss + l + 32]);
    float h0 = 0.f, h1 = 0.f;
    size_t base = (size_t)b * LL;

    for (int t0 = 0; t0 < LL; t0 += 16) {
        __syncthreads();
        for (int i = tid; i < 2048; i += 512) {
            int tt = i >> 7, c = i & 127;
            float val = xdbc[(base + t0 + tt) * 160 + 32 + c];
            if (c < 64) sB[tt][c] = val; else sC[tt][c - 64] = val;
        }
        if (tid < 256) {
            sdt[tid >> 4][tid & 15] = delta[(base + t0 + (tid >> 4)) * DI + d0 + (tid & 15)];
        } else {
            int jj = tid - 256;
            su[jj >> 4][jj & 15] = uact[(base + t0 + (jj >> 4)) * DI + d0 + (jj & 15)];
        }
        __syncthreads();
#pragma unroll 4
        for (int tt = 0; tt < 16; tt++) {
            float dt  = sdt[tt][w];
            float dtu = dt * su[tt][w];
            float dA0 = __expf(dt * a0);
            float dA1 = __expf(dt * a1);
            h0 = fmaf(h0, dA0, dtu * sB[tt][l]);
            h1 = fmaf(h1, dA1, dtu * sB[tt][l + 32]);
            float yv = h0 * sC[tt][l] + h1 * sC[tt][l + 32];
#pragma unroll
            for (int offx = 16; offx > 0; offx >>= 1)
                yv += __shfl_xor_sync(0xffffffffu, yv, offx);
            if (l == 0) y[(base + t0 + tt) * DI + d] = yv;
        }
    }
}

// ---------------- gate: y = (y + uact*D) * silu(z) ---------------------------
__global__ void gate_k(float* __restrict__ y, const float* __restrict__ uact,
                       const float* __restrict__ xz, const float* __restrict__ Dssm)
{
    int idx = blockIdx.x * 256 + threadIdx.x;
    int r = idx >> 10, j = idx & 1023;
    float z  = xz[(size_t)r * (2*DI) + DI + j];
    float yv = y[idx] + uact[idx] * Dssm[j];
    y[idx] = yv * (z / (1.f + expf(-z)));
}

// ---------------- fused residual-sum + LN1 + LN2 -----------------------------
__device__ __forceinline__ float blockSum128(float v, float* sm)
{
#pragma unroll
    for (int offx = 16; offx > 0; offx >>= 1)
        v += __shfl_xor_sync(0xffffffffu, v, offx);
    if ((threadIdx.x & 31) == 0) sm[threadIdx.x >> 5] = v;
    __syncthreads();
    float r = sm[0] + sm[1] + sm[2] + sm[3];
    __syncthreads();
    return r;
}

__global__ __launch_bounds__(128) void combine_ln_k(
    const float* __restrict__ xf, const float* __restrict__ attn,
    const float* __restrict__ mamba,
    const float* __restrict__ g1, const float* __restrict__ b1,
    const float* __restrict__ g2, const float* __restrict__ b2,
    float* __restrict__ h, float* __restrict__ hn)
{
    __shared__ float sm[4];
    int r = blockIdx.x, tid = threadIdx.x;
    size_t base = (size_t)r * Dd;
    float vv[4];
#pragma unroll
    for (int i = 0; i < 4; i++) {
        int c = tid + i*128;
        vv[i] = xf[base+c] + attn[base+c] + mamba[base+c];
    }
    float s = vv[0] + vv[1] + vv[2] + vv[3];
    float mean = blockSum128(s, sm) * (1.f/512.f);
    float sq = 0.f;
#pragma unroll
    for (int i = 0; i < 4; i++) { float dd = vv[i] - mean; sq = fmaf(dd, dd, sq); }
    float var = blockSum128(sq, sm) * (1.f/512.f);
    float inv = rsqrtf(var + 1e-5f);
    float hv[4];
#pragma unroll
    for (int i = 0; i < 4; i++) {
        int c = tid + i*128;
        hv[i] = (vv[i] - mean) * inv * g1[c] + b1[c];
        h[base+c] = hv[i];
    }
    float s2 = hv[0] + hv[1] + hv[2] + hv[3];
    float mean2 = blockSum128(s2, sm) * (1.f/512.f);
    float sq2 = 0.f;
#pragma unroll
    for (int i = 0; i < 4; i++) { float dd = hv[i] - mean2; sq2 = fmaf(dd, dd, sq2); }
    float var2 = blockSum128(sq2, sm) * (1.f/512.f);
    float inv2 = rsqrtf(var2 + 1e-6f);
#pragma unroll
    for (int i = 0; i < 4; i++) {
        int c = tid + i*128;
        hn[base+c] = (hv[i] - mean2) * inv2 * g2[c] + b2[c];
    }
}

// ---------------- launch -----------------------------------------------------
extern "C" void kernel_launch(void* const* d_in, const int* in_sizes, int n_in,
                              void* d_out, int out_size)
{
    const float* x            = (const float*)d_in[0];
    const unsigned char* mask = (const unsigned char*)d_in[1];
    const float* Wq = (const float*)d_in[2];   const float* bq = (const float*)d_in[3];
    const float* Wk = (const float*)d_in[4];   const float* bk = (const float*)d_in[5];
    const float* Wv = (const float*)d_in[6];   const float* bv = (const float*)d_in[7];
    const float* Wo = (const float*)d_in[8];   const float* bo = (const float*)d_in[9];
    const float* in_proj_w = (const float*)d_in[10];
    const float* conv_w    = (const float*)d_in[11];
    const float* conv_b    = (const float*)d_in[12];
    const float* x_proj_w  = (const float*)d_in[13];
    const float* dt_proj_w = (const float*)d_in[14];
    const float* dt_proj_b = (const float*)d_in[15];
    const float* A_log     = (const float*)d_in[16];
    const float* D_ssm     = (const float*)d_in[17];
    const float* out_proj_w= (const float*)d_in[18];
    const float* ln1_g = (const float*)d_in[19]; const float* ln1_b = (const float*)d_in[20];
    const float* ffn_w1= (const float*)d_in[21]; const float* ffn_b1= (const float*)d_in[22];
    const float* ffn_w2= (const float*)d_in[23]; const float* ffn_b2= (const float*)d_in[24];
    const float* ln2_g = (const float*)d_in[25]; const float* ln2_b = (const float*)d_in[26];
    float* out = (float*)d_out;

    float *q,*k,*v,*attnO,*attn_out,*xz,*uact,*xdbc,*delta,*y,*mamba,*h,*hn,*mid;
    cudaGetSymbolAddress((void**)&q,        g_q);
    cudaGetSymbolAddress((void**)&k,        g_k);
    cudaGetSymbolAddress((void**)&v,        g_v);
    cudaGetSymbolAddress((void**)&attnO,    g_attnO);
    cudaGetSymbolAddress((void**)&attn_out, g_attn_out);
    cudaGetSymbolAddress((void**)&xz,       g_xz);
    cudaGetSymbolAddress((void**)&uact,     g_uact);
    cudaGetSymbolAddress((void**)&xdbc,     g_xdbc);
    cudaGetSymbolAddress((void**)&delta,    g_delta);
    cudaGetSymbolAddress((void**)&y,        g_y);
    cudaGetSymbolAddress((void**)&mamba,    g_mamba);
    cudaGetSymbolAddress((void**)&h,        g_h);
    cudaGetSymbolAddress((void**)&hn,       g_hn);
    cudaGetSymbolAddress((void**)&mid,      g_mid);

    // persistent secondary stream + fork/join events (created once; host-side
    // objects, no device allocation; identical launch pattern on every call)
    static cudaStream_t s_attn = nullptr;
    static cudaEvent_t  e_fork = nullptr, e_join = nullptr;
    if (s_attn == nullptr) {
        cudaStreamCreateWithFlags(&s_attn, cudaStreamNonBlocking);
        cudaEventCreateWithFlags(&e_fork, cudaEventDisableTiming);
        cudaEventCreateWithFlags(&e_join, cudaEventDisableTiming);
    }

    const int MY = Mrows / 128;   // 72
    const int attn_smem = (2*64*68 + 8*16*68) * 4;   // 69632 bytes
    cudaFuncSetAttribute(attn_tc, cudaFuncAttributeMaxDynamicSharedMemorySize, attn_smem);

    // ---- fork: attention branch runs on s_attn, mamba branch on stream 0 ----
    cudaEventRecord(e_fork, 0);
    cudaStreamWaitEvent(s_attn, e_fork, 0);

    // attention branch (s_attn)
    gemm_bf16<EPI_NONE><<<dim3(Dd/64,   MY), 256, 0, s_attn>>>(x, Dd, Wq, bq, nullptr, q, Mrows, Dd, Dd);
    gemm_bf16<EPI_NONE><<<dim3(Dd/64,   MY), 256, 0, s_attn>>>(x, Dd, Wk, bk, nullptr, k, Mrows, Dd, Dd);
    gemm_bf16<EPI_NONE><<<dim3(Dd/64,   MY), 256, 0, s_attn>>>(x, Dd, Wv, bv, nullptr, v, Mrows, Dd, Dd);
    attn_tc<<<dim3(LL/128, Hh, Bsz), 256, attn_smem, s_attn>>>(q, k, v, mask, attnO);
    gemm_bf16<EPI_NONE><<<dim3(Dd/64,   MY), 256, 0, s_attn>>>(attnO, Dd, Wo, bo, nullptr, attn_out, Mrows, Dd, Dd);
    cudaEventRecord(e_join, s_attn);

    // mamba branch (stream 0)
    gemm_bf16<EPI_NONE><<<dim3(2*DI/64, MY), 256>>>(x, Dd, in_proj_w, nullptr, nullptr, xz, Mrows, 2*DI, Dd);
    conv_silu_k<<<Mrows*DI/256, 256>>>(xz, conv_w, conv_b, uact);
    gemm_tf32<EPI_NONE><<<dim3(3,       MY), 256>>>(uact, DI, x_proj_w, nullptr, nullptr, xdbc, Mrows, 160, DI);
    gemm_tf32<EPI_SOFTPLUS><<<dim3(DI/64, MY), 256>>>(xdbc, 160, dt_proj_w, dt_proj_b, nullptr, delta, Mrows, DI, Rr);
    scan_k<<<dim3(DI/16, Bsz), 512>>>(delta, uact, xdbc, A_log, y);
    gate_k<<<Mrows*DI/256, 256>>>(y, uact, xz, D_ssm);
    gemm_bf16<EPI_NONE><<<dim3(Dd/64,   MY), 256>>>(y, DI, out_proj_w, nullptr, nullptr, mamba, Mrows, Dd, DI);

    // ---- join ----
    cudaStreamWaitEvent(0, e_join, 0);

    // combine + double layernorm
    combine_ln_k<<<Mrows, 128>>>(x, attn_out, mamba, ln1_g, ln1_b, ln2_g, ln2_b, h, hn);

    // FFN
    gemm_bf16<EPI_GELU><<<dim3(DFF/64, MY), 256>>>(hn, Dd, ffn_w1, ffn_b1, nullptr, mid, Mrows, DFF, Dd);
    gemm_bf16<EPI_ADD><<<dim3(Dd/64,   MY), 256>>>(mid, DFF, ffn_w2, ffn_b2, h, out, Mrows, Dd, DFF);
}